// round 13
// baseline (speedup 1.0000x reference)
#include <cuda_runtime.h>
#include <cuda_bf16.h>
#include <cstdint>

// Problem constants
#define Bb 2
#define Ss 2048
#define Dd 1024
#define Hh 16
#define Kk 64
#define BH (Bb*Hh)          // 32
#define SCALE 0.125f

// ---------------- scratch (static device globals) ----------------
#define QKSZ ((size_t)BH*Ss*Kk)   // 4,194,304

__device__ float g_Q[QKSZ];                          // [bh][s][k]
__device__ float g_K[QKSZ];
__device__ float g_V[QKSZ];
__device__ float g_heads[(size_t)Bb*Ss*Hh*Kk];       // [b][s][hk]
__device__ float g_inv[(size_t)BH*Ss];               // per row: 1/sum(exp)

// 64-FMA micro-kernel helper
#define MICRO_FMA(acc, a0, a1, b0, b1)                                   \
    {                                                                    \
        float _a[8] = {a0.x, a0.y, a0.z, a0.w, a1.x, a1.y, a1.z, a1.w};  \
        float _b[8] = {b0.x, b0.y, b0.z, b0.w, b1.x, b1.y, b1.z, b1.w};  \
        _Pragma("unroll")                                                \
        for (int _i = 0; _i < 8; _i++) {                                 \
            _Pragma("unroll")                                            \
            for (int _j = 0; _j < 8; _j++)                               \
                acc[_i][_j] += _a[_i] * _b[_j];                          \
        }                                                                \
    }

// ============================================================================
// Kernel 1 (R5, verbatim): QKV projection. grid (16, BH, 3), 128 threads
// ============================================================================
__global__ __launch_bounds__(128) void qkv_kernel(
    const float* __restrict__ x,
    const float* __restrict__ W_Q, const float* __restrict__ b_Q,
    const float* __restrict__ W_K, const float* __restrict__ b_K,
    const float* __restrict__ W_V, const float* __restrict__ b_V)
{
    const int stile = blockIdx.x;
    const int bh    = blockIdx.y;
    const int which = blockIdx.z;
    const int b = bh / Hh, h = bh % Hh;

    const float* W    = (which == 0) ? W_Q : (which == 1) ? W_K : W_V;
    const float* bias = (which == 0) ? b_Q : (which == 1) ? b_K : b_V;
    float*       out  = (which == 0) ? g_Q : (which == 1) ? g_K : g_V;

    __shared__ float At[32][132];
    __shared__ float Bs[32][68];

    const int tid = threadIdx.x;
    const int s0 = stile * 128;
    const float* Ax = x + ((size_t)b * Ss + s0) * Dd;
    const float* Wh = W + (size_t)h * Dd * Kk;

    const int r0 = (tid >> 3) << 3;
    const int c0 = (tid & 7) << 3;

    float acc[8][8];
    #pragma unroll
    for (int i = 0; i < 8; i++)
        #pragma unroll
        for (int j = 0; j < 8; j++) acc[i][j] = 0.f;

    for (int d0 = 0; d0 < Dd; d0 += 32) {
        #pragma unroll
        for (int it = 0; it < 8; it++) {
            const int idx = it * 128 + tid;
            const int row = idx >> 3;
            const int k4  = (idx & 7) << 2;
            const float4 v = *(const float4*)&Ax[(size_t)row * Dd + d0 + k4];
            At[k4 + 0][row] = v.x; At[k4 + 1][row] = v.y;
            At[k4 + 2][row] = v.z; At[k4 + 3][row] = v.w;
        }
        #pragma unroll
        for (int it = 0; it < 4; it++) {
            const int idx = it * 128 + tid;
            const int dd = idx >> 4;
            const int c4 = (idx & 15) << 2;
            *(float4*)&Bs[dd][c4] = *(const float4*)&Wh[(size_t)(d0 + dd) * Kk + c4];
        }
        __syncthreads();
        #pragma unroll
        for (int dd = 0; dd < 32; dd++) {
            const float4 a0 = *(const float4*)&At[dd][r0];
            const float4 a1 = *(const float4*)&At[dd][r0 + 4];
            const float4 b0 = *(const float4*)&Bs[dd][c0];
            const float4 b1 = *(const float4*)&Bs[dd][c0 + 4];
            MICRO_FMA(acc, a0, a1, b0, b1);
        }
        __syncthreads();
    }

    float bv[8];
    #pragma unroll
    for (int j = 0; j < 8; j++) bv[j] = bias[h * Kk + c0 + j];

    float* outp = out + ((size_t)bh * Ss + s0) * Kk;
    #pragma unroll
    for (int i = 0; i < 8; i++) {
        float4 o0, o1;
        o0.x = acc[i][0] + bv[0]; o0.y = acc[i][1] + bv[1];
        o0.z = acc[i][2] + bv[2]; o0.w = acc[i][3] + bv[3];
        o1.x = acc[i][4] + bv[4]; o1.y = acc[i][5] + bv[5];
        o1.z = acc[i][6] + bv[6]; o1.w = acc[i][7] + bv[7];
        *(float4*)&outp[(size_t)(r0 + i) * Kk + c0]     = o0;
        *(float4*)&outp[(size_t)(r0 + i) * Kk + c0 + 4] = o1;
    }
}

// ============================================================================
// Kernel 2: scores with FUSED exp.  E = mask ? exp(score*SCALE) : 0.
// No max subtraction: scores are ~N(0,1) after scaling (max ~6 over 134M),
// exp cannot overflow fp32.  grid (Hh, 256, Bb), 256 threads.
// ============================================================================
__global__ __launch_bounds__(256) void scores_kernel(
    const int* __restrict__ mask, float* __restrict__ out_scores)
{
    extern __shared__ float sm[];
    float (*Qt)[132] = (float(*)[132])sm;
    float (*Kt)[132] = (float(*)[132])(sm + 64 * 132);

    const int h  = blockIdx.x;
    const int b  = blockIdx.z;
    const int bh = b * Hh + h;
    const int st = blockIdx.y & 15;
    const int tt = blockIdx.y >> 4;
    const int s0 = st * 128;
    const int t0 = tt * 128;
    const int tid = threadIdx.x;

    const float* Qg = g_Q + ((size_t)bh * Ss + s0) * Kk;
    const float* Kg = g_K + ((size_t)bh * Ss + t0) * Kk;

    #pragma unroll
    for (int it = 0; it < 8; it++) {
        const int idx = it * 256 + tid;
        const int row = idx >> 4;
        const int k4  = (idx & 15) << 2;
        const float4 q = *(const float4*)&Qg[(size_t)row * Kk + k4];
        Qt[k4 + 0][row] = q.x; Qt[k4 + 1][row] = q.y;
        Qt[k4 + 2][row] = q.z; Qt[k4 + 3][row] = q.w;
        const float4 k = *(const float4*)&Kg[(size_t)row * Kk + k4];
        Kt[k4 + 0][row] = k.x; Kt[k4 + 1][row] = k.y;
        Kt[k4 + 2][row] = k.z; Kt[k4 + 3][row] = k.w;
    }
    __syncthreads();

    const int r0 = (tid >> 4) << 3;
    const int c0 = (tid & 15) << 3;

    float acc[8][8];
    #pragma unroll
    for (int i = 0; i < 8; i++)
        #pragma unroll
        for (int j = 0; j < 8; j++) acc[i][j] = 0.f;

    #pragma unroll 8
    for (int k = 0; k < Kk; k++) {
        const float4 a0 = *(const float4*)&Qt[k][r0];
        const float4 a1 = *(const float4*)&Qt[k][r0 + 4];
        const float4 b0 = *(const float4*)&Kt[k][c0];
        const float4 b1 = *(const float4*)&Kt[k][c0 + 4];
        MICRO_FMA(acc, a0, a1, b0, b1);
    }

    #pragma unroll
    for (int i = 0; i < 8; i++) {
        const int s = s0 + r0 + i;
        const int* mrow = mask + ((size_t)b * Ss + s) * Ss + t0;
        const int4 m0 = *(const int4*)&mrow[c0];
        const int4 m1 = *(const int4*)&mrow[c0 + 4];
        float4 o0, o1;
        o0.x = m0.x ? __expf(acc[i][0] * SCALE) : 0.0f;
        o0.y = m0.y ? __expf(acc[i][1] * SCALE) : 0.0f;
        o0.z = m0.z ? __expf(acc[i][2] * SCALE) : 0.0f;
        o0.w = m0.w ? __expf(acc[i][3] * SCALE) : 0.0f;
        o1.x = m1.x ? __expf(acc[i][4] * SCALE) : 0.0f;
        o1.y = m1.y ? __expf(acc[i][5] * SCALE) : 0.0f;
        o1.z = m1.z ? __expf(acc[i][6] * SCALE) : 0.0f;
        o1.w = m1.w ? __expf(acc[i][7] * SCALE) : 0.0f;
        float* orow = out_scores + ((size_t)bh * Ss + s) * Ss + t0;
        *(float4*)&orow[c0]     = o0;
        *(float4*)&orow[c0 + 4] = o1;
    }
}

// ============================================================================
// Kernel 3: rowsum — per-row 1/sum over E.  Pure adds, memory bound.
// grid (BH*S), 256 threads.
// ============================================================================
__global__ __launch_bounds__(256) void rowsum_kernel(const float* __restrict__ E)
{
    __shared__ float red[8];
    const float4* row = (const float4*)(E + (size_t)blockIdx.x * Ss);
    const int tid = threadIdx.x, lane = tid & 31, warp = tid >> 5;

    const float4 v0 = row[tid];
    const float4 v1 = row[tid + 256];
    float sum = v0.x + v0.y + v0.z + v0.w + v1.x + v1.y + v1.z + v1.w;
    #pragma unroll
    for (int o = 16; o > 0; o >>= 1) sum += __shfl_xor_sync(0xffffffffu, sum, o);
    if (lane == 0) red[warp] = sum;
    __syncthreads();
    if (tid == 0) {
        float s = 0.f;
        #pragma unroll
        for (int i = 0; i < 8; i++) s += red[i];
        g_inv[blockIdx.x] = 1.0f / s;
    }
}

// ============================================================================
// Kernel 4: pv_fused — P = E * inv (FMUL only), write P back (output 1),
// heads = P @ V.  R5 pv structure: 128 threads, BM=128, BN=64, BK=32.
// grid (16, BH)
// ============================================================================
__global__ __launch_bounds__(128) void pv_fused(float* __restrict__ scores)
{
    __shared__ float Pt[32][132];   // Pt[t][row]
    __shared__ float Vs[32][68];    // Vs[t][col]
    __shared__ float sm_inv[128];

    const int bh = blockIdx.y;
    const int b = bh / Hh, h = bh % Hh;
    const int s0 = blockIdx.x * 128;
    const int tid = threadIdx.x;

    float* Pg = scores + ((size_t)bh * Ss + s0) * Ss;
    const float* Vg = g_V + (size_t)bh * Ss * Kk;

    sm_inv[tid] = g_inv[(size_t)bh * Ss + s0 + tid];
    __syncthreads();

    const int r0 = (tid >> 3) << 3;
    const int c0 = (tid & 7) << 3;

    float acc[8][8];
    #pragma unroll
    for (int i = 0; i < 8; i++)
        #pragma unroll
        for (int j = 0; j < 8; j++) acc[i][j] = 0.f;

    for (int t0 = 0; t0 < Ss; t0 += 32) {
        // load E tile, normalize (FMUL), write P back, transpose into smem
        #pragma unroll
        for (int it = 0; it < 8; it++) {
            const int idx = it * 128 + tid;
            const int row = idx >> 3;
            const int q4  = (idx & 7) << 2;
            const float inv = sm_inv[row];
            float* paddr = &Pg[(size_t)row * Ss + t0 + q4];
            float4 v = *(const float4*)paddr;
            v.x *= inv; v.y *= inv; v.z *= inv; v.w *= inv;
            *(float4*)paddr = v;               // normalized probs -> output 1
            Pt[q4 + 0][row] = v.x; Pt[q4 + 1][row] = v.y;
            Pt[q4 + 2][row] = v.z; Pt[q4 + 3][row] = v.w;
        }
        // load V tile (32 x 64)
        #pragma unroll
        for (int it = 0; it < 4; it++) {
            const int idx = it * 128 + tid;
            const int tt = idx >> 4;
            const int c4 = (idx & 15) << 2;
            *(float4*)&Vs[tt][c4] = *(const float4*)&Vg[(size_t)(t0 + tt) * Kk + c4];
        }
        __syncthreads();
        #pragma unroll
        for (int tt = 0; tt < 32; tt++) {
            const float4 a0 = *(const float4*)&Pt[tt][r0];
            const float4 a1 = *(const float4*)&Pt[tt][r0 + 4];
            const float4 b0 = *(const float4*)&Vs[tt][c0];
            const float4 b1 = *(const float4*)&Vs[tt][c0 + 4];
            MICRO_FMA(acc, a0, a1, b0, b1);
        }
        __syncthreads();
    }

    #pragma unroll
    for (int i = 0; i < 8; i++) {
        float* orow = g_heads + ((size_t)(b * Ss + s0 + r0 + i)) * (Hh * Kk) + h * Kk;
        float4 o0, o1;
        o0.x = acc[i][0]; o0.y = acc[i][1]; o0.z = acc[i][2]; o0.w = acc[i][3];
        o1.x = acc[i][4]; o1.y = acc[i][5]; o1.z = acc[i][6]; o1.w = acc[i][7];
        *(float4*)&orow[c0]     = o0;
        *(float4*)&orow[c0 + 4] = o1;
    }
}

// ============================================================================
// Kernel 5 (R5, verbatim): output projection. grid (16, 32), 128 threads
// ============================================================================
__global__ __launch_bounds__(128) void proj_kernel(
    const float* __restrict__ Wp, const float* __restrict__ bp,
    float* __restrict__ out)
{
    __shared__ float At[32][132];
    __shared__ float Bs[32][68];

    const int tid = threadIdx.x;
    const int n0 = blockIdx.x * 64;
    const int m0 = blockIdx.y * 128;
    const int HK = Hh * Kk;   // 1024

    const float* A = g_heads + (size_t)m0 * HK;

    const int r0 = (tid >> 3) << 3;
    const int c0 = (tid & 7) << 3;

    float acc[8][8];
    #pragma unroll
    for (int i = 0; i < 8; i++)
        #pragma unroll
        for (int j = 0; j < 8; j++) acc[i][j] = 0.f;

    for (int d0 = 0; d0 < HK; d0 += 32) {
        #pragma unroll
        for (int it = 0; it < 8; it++) {
            const int idx = it * 128 + tid;
            const int row = idx >> 3;
            const int k4  = (idx & 7) << 2;
            const float4 v = *(const float4*)&A[(size_t)row * HK + d0 + k4];
            At[k4 + 0][row] = v.x; At[k4 + 1][row] = v.y;
            At[k4 + 2][row] = v.z; At[k4 + 3][row] = v.w;
        }
        #pragma unroll
        for (int it = 0; it < 4; it++) {
            const int idx = it * 128 + tid;
            const int dd = idx >> 4;
            const int c4 = (idx & 15) << 2;
            *(float4*)&Bs[dd][c4] = *(const float4*)&Wp[(size_t)(d0 + dd) * Dd + n0 + c4];
        }
        __syncthreads();
        #pragma unroll
        for (int dd = 0; dd < 32; dd++) {
            const float4 a0 = *(const float4*)&At[dd][r0];
            const float4 a1 = *(const float4*)&At[dd][r0 + 4];
            const float4 b0 = *(const float4*)&Bs[dd][c0];
            const float4 b1 = *(const float4*)&Bs[dd][c0 + 4];
            MICRO_FMA(acc, a0, a1, b0, b1);
        }
        __syncthreads();
    }

    float bv[8];
    #pragma unroll
    for (int j = 0; j < 8; j++) bv[j] = bp[n0 + c0 + j];

    #pragma unroll
    for (int i = 0; i < 8; i++) {
        float4 o0, o1;
        o0.x = acc[i][0] + bv[0]; o0.y = acc[i][1] + bv[1];
        o0.z = acc[i][2] + bv[2]; o0.w = acc[i][3] + bv[3];
        o1.x = acc[i][4] + bv[4]; o1.y = acc[i][5] + bv[5];
        o1.z = acc[i][6] + bv[6]; o1.w = acc[i][7] + bv[7];
        *(float4*)&out[(size_t)(m0 + r0 + i) * Dd + n0 + c0]     = o0;
        *(float4*)&out[(size_t)(m0 + r0 + i) * Dd + n0 + c0 + 4] = o1;
    }
}

// ============================================================================
extern "C" void kernel_launch(void* const* d_in, const int* in_sizes, int n_in,
                              void* d_out, int out_size)
{
    const float* x      = (const float*)d_in[0];
    const float* W_Q    = (const float*)d_in[1];
    const float* b_Q    = (const float*)d_in[2];
    const float* W_K    = (const float*)d_in[3];
    const float* b_K    = (const float*)d_in[4];
    const float* W_V    = (const float*)d_in[5];
    const float* b_V    = (const float*)d_in[6];
    const float* W_proj = (const float*)d_in[7];
    const float* b_proj = (const float*)d_in[8];
    const int*   amask  = (const int*)d_in[9];

    float* out        = (float*)d_out;                  // [B,S,D]
    float* out_scores = out + (size_t)Bb * Ss * Dd;     // [B,H,S,S]

    // 1) QKV projections
    qkv_kernel<<<dim3(16, BH, 3), 128>>>(x, W_Q, b_Q, W_K, b_K, W_V, b_V);

    // 2) masked scores with fused exp -> E in out_scores
    {
        const int smem = 2 * 64 * 132 * (int)sizeof(float);   // 67.6 KB (proven)
        cudaFuncSetAttribute(scores_kernel, cudaFuncAttributeMaxDynamicSharedMemorySize, smem);
        scores_kernel<<<dim3(Hh, 256, Bb), 256, smem>>>(amask, out_scores);
    }

    // 3) per-row 1/sum (no exp)
    rowsum_kernel<<<BH * Ss, 256>>>(out_scores);

    // 4) fused normalize (FMUL) + write probs + P @ V
    pv_fused<<<dim3(16, BH), 128>>>(out_scores);

    // 5) output projection
    proj_kernel<<<dim3(16, (Bb * Ss) / 128), 128>>>(W_proj, b_proj, out);
}

// round 14
// speedup vs baseline: 1.4837x; 1.4837x over previous
#include <cuda_runtime.h>
#include <cuda_bf16.h>
#include <cstdint>

// Problem constants
#define Bb 2
#define Ss 2048
#define Dd 1024
#define Hh 16
#define Kk 64
#define BH (Bb*Hh)          // 32
#define SCALE 0.125f
#define NEGF  (-3.402823466e38f)

// ---------------- scratch (static device globals) ----------------
#define QKSZ ((size_t)BH*Ss*Kk)   // 4,194,304

__device__ float g_Q[QKSZ];                          // [bh][s][k]
__device__ float g_K[QKSZ];
__device__ float g_V[QKSZ];
__device__ float g_heads[(size_t)Bb*Ss*Hh*Kk];       // [b][s][hk]
__device__ __nv_bfloat16 g_Vthi[QKSZ], g_Vtlo[QKSZ]; // V^T split [bh][k][s]
__device__ int g_mma_ok;                             // probe result

// ============================ helpers =======================================
__device__ __forceinline__ uint32_t pk2(float lo_, float hi_){
    uint32_t r;
    asm("cvt.rn.bf16x2.f32 %0, %1, %2;" : "=r"(r) : "f"(hi_), "f"(lo_));
    return r;
}
__device__ __forceinline__ void split8(const float* v, uint4& hi, uint4& lo){
    float h[8];
    #pragma unroll
    for (int i = 0; i < 8; i++) h[i] = __bfloat162float(__float2bfloat16_rn(v[i]));
    hi.x = pk2(h[0], h[1]); hi.y = pk2(h[2], h[3]);
    hi.z = pk2(h[4], h[5]); hi.w = pk2(h[6], h[7]);
    lo.x = pk2(v[0]-h[0], v[1]-h[1]); lo.y = pk2(v[2]-h[2], v[3]-h[3]);
    lo.z = pk2(v[4]-h[4], v[5]-h[5]); lo.w = pk2(v[6]-h[6], v[7]-h[7]);
}
__device__ __forceinline__ void mma16816(float* c, const uint32_t a[4], const uint32_t b[2]){
    asm volatile("mma.sync.aligned.m16n8k16.row.col.f32.bf16.bf16.f32 "
        "{%0,%1,%2,%3}, {%4,%5,%6,%7}, {%8,%9}, {%0,%1,%2,%3};"
        : "+f"(c[0]), "+f"(c[1]), "+f"(c[2]), "+f"(c[3])
        : "r"(a[0]), "r"(a[1]), "r"(a[2]), "r"(a[3]), "r"(b[0]), "r"(b[1]));
}

// 64-FMA micro-kernel helper
#define MICRO_FMA(acc, a0, a1, b0, b1)                                   \
    {                                                                    \
        float _a[8] = {a0.x, a0.y, a0.z, a0.w, a1.x, a1.y, a1.z, a1.w};  \
        float _b[8] = {b0.x, b0.y, b0.z, b0.w, b1.x, b1.y, b1.z, b1.w};  \
        _Pragma("unroll")                                                \
        for (int _i = 0; _i < 8; _i++) {                                 \
            _Pragma("unroll")                                            \
            for (int _j = 0; _j < 8; _j++)                               \
                acc[_i][_j] += _a[_i] * _b[_j];                          \
        }                                                                \
    }

// mma-path smem geometry: rows padded to 80 B -> conflict-free word idx 20r+tg
#define RS2    80
#define A32SZ  (128*RS2)    // 10240
#define B32SZ  (64*RS2)     // 5120
#define SBUF_BYTES (2*A32SZ + 2*B32SZ)   // 30720

__device__ __forceinline__ void frag_a32(uint32_t (&a)[4], const char* base, int row, int kb){
    a[0] = *(const uint32_t*)(base + (size_t)row       * RS2 + kb);
    a[1] = *(const uint32_t*)(base + (size_t)(row + 8) * RS2 + kb);
    a[2] = *(const uint32_t*)(base + (size_t)row       * RS2 + kb + 16);
    a[3] = *(const uint32_t*)(base + (size_t)(row + 8) * RS2 + kb + 16);
}
__device__ __forceinline__ void frag_b32(uint32_t (&b)[2], const char* base, int row, int kb){
    b[0] = *(const uint32_t*)(base + (size_t)row * RS2 + kb);
    b[1] = *(const uint32_t*)(base + (size_t)row * RS2 + kb + 16);
}

// ============================================================================
// Kernel 1 (R5, verbatim): QKV projection. grid (16, BH, 3), 128 threads
// ============================================================================
__global__ __launch_bounds__(128) void qkv_kernel(
    const float* __restrict__ x,
    const float* __restrict__ W_Q, const float* __restrict__ b_Q,
    const float* __restrict__ W_K, const float* __restrict__ b_K,
    const float* __restrict__ W_V, const float* __restrict__ b_V)
{
    const int stile = blockIdx.x;
    const int bh    = blockIdx.y;
    const int which = blockIdx.z;
    const int b = bh / Hh, h = bh % Hh;

    const float* W    = (which == 0) ? W_Q : (which == 1) ? W_K : W_V;
    const float* bias = (which == 0) ? b_Q : (which == 1) ? b_K : b_V;
    float*       out  = (which == 0) ? g_Q : (which == 1) ? g_K : g_V;

    __shared__ float At[32][132];
    __shared__ float Bs[32][68];

    const int tid = threadIdx.x;
    const int s0 = stile * 128;
    const float* Ax = x + ((size_t)b * Ss + s0) * Dd;
    const float* Wh = W + (size_t)h * Dd * Kk;

    const int r0 = (tid >> 3) << 3;
    const int c0 = (tid & 7) << 3;

    float acc[8][8];
    #pragma unroll
    for (int i = 0; i < 8; i++)
        #pragma unroll
        for (int j = 0; j < 8; j++) acc[i][j] = 0.f;

    for (int d0 = 0; d0 < Dd; d0 += 32) {
        #pragma unroll
        for (int it = 0; it < 8; it++) {
            const int idx = it * 128 + tid;
            const int row = idx >> 3;
            const int k4  = (idx & 7) << 2;
            const float4 v = *(const float4*)&Ax[(size_t)row * Dd + d0 + k4];
            At[k4 + 0][row] = v.x; At[k4 + 1][row] = v.y;
            At[k4 + 2][row] = v.z; At[k4 + 3][row] = v.w;
        }
        #pragma unroll
        for (int it = 0; it < 4; it++) {
            const int idx = it * 128 + tid;
            const int dd = idx >> 4;
            const int c4 = (idx & 15) << 2;
            *(float4*)&Bs[dd][c4] = *(const float4*)&Wh[(size_t)(d0 + dd) * Kk + c4];
        }
        __syncthreads();
        #pragma unroll
        for (int dd = 0; dd < 32; dd++) {
            const float4 a0 = *(const float4*)&At[dd][r0];
            const float4 a1 = *(const float4*)&At[dd][r0 + 4];
            const float4 b0 = *(const float4*)&Bs[dd][c0];
            const float4 b1 = *(const float4*)&Bs[dd][c0 + 4];
            MICRO_FMA(acc, a0, a1, b0, b1);
        }
        __syncthreads();
    }

    float bv[8];
    #pragma unroll
    for (int j = 0; j < 8; j++) bv[j] = bias[h * Kk + c0 + j];

    float* outp = out + ((size_t)bh * Ss + s0) * Kk;
    #pragma unroll
    for (int i = 0; i < 8; i++) {
        float4 o0, o1;
        o0.x = acc[i][0] + bv[0]; o0.y = acc[i][1] + bv[1];
        o0.z = acc[i][2] + bv[2]; o0.w = acc[i][3] + bv[3];
        o1.x = acc[i][4] + bv[4]; o1.y = acc[i][5] + bv[5];
        o1.z = acc[i][6] + bv[6]; o1.w = acc[i][7] + bv[7];
        *(float4*)&outp[(size_t)(r0 + i) * Kk + c0]     = o0;
        *(float4*)&outp[(size_t)(r0 + i) * Kk + c0 + 4] = o1;
    }
}

// ============================================================================
// Kernel 2 (R5, verbatim): masked scaled scores. grid (Hh, 256, Bb), 256 thr
// ============================================================================
__global__ __launch_bounds__(256) void scores_kernel(
    const int* __restrict__ mask, float* __restrict__ out_scores)
{
    extern __shared__ float sm[];
    float (*Qt)[132] = (float(*)[132])sm;
    float (*Kt)[132] = (float(*)[132])(sm + 64 * 132);

    const int h  = blockIdx.x;
    const int b  = blockIdx.z;
    const int bh = b * Hh + h;
    const int st = blockIdx.y & 15;
    const int tt = blockIdx.y >> 4;
    const int s0 = st * 128;
    const int t0 = tt * 128;
    const int tid = threadIdx.x;

    const float* Qg = g_Q + ((size_t)bh * Ss + s0) * Kk;
    const float* Kg = g_K + ((size_t)bh * Ss + t0) * Kk;

    #pragma unroll
    for (int it = 0; it < 8; it++) {
        const int idx = it * 256 + tid;
        const int row = idx >> 4;
        const int k4  = (idx & 15) << 2;
        const float4 q = *(const float4*)&Qg[(size_t)row * Kk + k4];
        Qt[k4 + 0][row] = q.x; Qt[k4 + 1][row] = q.y;
        Qt[k4 + 2][row] = q.z; Qt[k4 + 3][row] = q.w;
        const float4 k = *(const float4*)&Kg[(size_t)row * Kk + k4];
        Kt[k4 + 0][row] = k.x; Kt[k4 + 1][row] = k.y;
        Kt[k4 + 2][row] = k.z; Kt[k4 + 3][row] = k.w;
    }
    __syncthreads();

    const int r0 = (tid >> 4) << 3;
    const int c0 = (tid & 15) << 3;

    float acc[8][8];
    #pragma unroll
    for (int i = 0; i < 8; i++)
        #pragma unroll
        for (int j = 0; j < 8; j++) acc[i][j] = 0.f;

    #pragma unroll 8
    for (int k = 0; k < Kk; k++) {
        const float4 a0 = *(const float4*)&Qt[k][r0];
        const float4 a1 = *(const float4*)&Qt[k][r0 + 4];
        const float4 b0 = *(const float4*)&Kt[k][c0];
        const float4 b1 = *(const float4*)&Kt[k][c0 + 4];
        MICRO_FMA(acc, a0, a1, b0, b1);
    }

    #pragma unroll
    for (int i = 0; i < 8; i++) {
        const int s = s0 + r0 + i;
        const int* mrow = mask + ((size_t)b * Ss + s) * Ss + t0;
        const int4 m0 = *(const int4*)&mrow[c0];
        const int4 m1 = *(const int4*)&mrow[c0 + 4];
        float4 o0, o1;
        o0.x = m0.x ? acc[i][0] * SCALE : NEGF;
        o0.y = m0.y ? acc[i][1] * SCALE : NEGF;
        o0.z = m0.z ? acc[i][2] * SCALE : NEGF;
        o0.w = m0.w ? acc[i][3] * SCALE : NEGF;
        o1.x = m1.x ? acc[i][4] * SCALE : NEGF;
        o1.y = m1.y ? acc[i][5] * SCALE : NEGF;
        o1.z = m1.z ? acc[i][6] * SCALE : NEGF;
        o1.w = m1.w ? acc[i][7] * SCALE : NEGF;
        float* orow = out_scores + ((size_t)bh * Ss + s) * Ss + t0;
        *(float4*)&orow[c0]     = o0;
        *(float4*)&orow[c0 + 4] = o1;
    }
}

// ============================================================================
// Kernel 3 (R5, verbatim): in-place row softmax. grid (BH*S), 256 threads
// ============================================================================
__global__ __launch_bounds__(256) void softmax_kernel(float* __restrict__ scores)
{
    __shared__ float red[8];
    __shared__ float bcast;

    float4* row = (float4*)(scores + (size_t)blockIdx.x * Ss);
    const int tid = threadIdx.x;
    const int lane = tid & 31, warp = tid >> 5;

    float4 v0 = row[tid];
    float4 v1 = row[tid + 256];

    float mx = fmaxf(fmaxf(fmaxf(v0.x, v0.y), fmaxf(v0.z, v0.w)),
                     fmaxf(fmaxf(v1.x, v1.y), fmaxf(v1.z, v1.w)));
    #pragma unroll
    for (int o = 16; o > 0; o >>= 1) mx = fmaxf(mx, __shfl_xor_sync(0xffffffffu, mx, o));
    if (lane == 0) red[warp] = mx;
    __syncthreads();
    if (tid == 0) {
        float m = red[0];
        #pragma unroll
        for (int i = 1; i < 8; i++) m = fmaxf(m, red[i]);
        bcast = m;
    }
    __syncthreads();
    mx = bcast;

    v0.x = __expf(v0.x - mx); v0.y = __expf(v0.y - mx);
    v0.z = __expf(v0.z - mx); v0.w = __expf(v0.w - mx);
    v1.x = __expf(v1.x - mx); v1.y = __expf(v1.y - mx);
    v1.z = __expf(v1.z - mx); v1.w = __expf(v1.w - mx);
    float sum = v0.x + v0.y + v0.z + v0.w + v1.x + v1.y + v1.z + v1.w;
    #pragma unroll
    for (int o = 16; o > 0; o >>= 1) sum += __shfl_xor_sync(0xffffffffu, sum, o);
    __syncthreads();
    if (lane == 0) red[warp] = sum;
    __syncthreads();
    if (tid == 0) {
        float s = 0.f;
        #pragma unroll
        for (int i = 0; i < 8; i++) s += red[i];
        bcast = 1.0f / s;
    }
    __syncthreads();
    const float inv = bcast;

    v0.x *= inv; v0.y *= inv; v0.z *= inv; v0.w *= inv;
    v1.x *= inv; v1.y *= inv; v1.z *= inv; v1.w *= inv;
    row[tid]       = v0;
    row[tid + 256] = v1;
}

// ============================================================================
// Kernel 4: vsplit — transpose+split g_V fp32 -> Vt hi/lo [bh][k][s]
// grid (32, BH), 256 threads
// ============================================================================
__global__ __launch_bounds__(256) void vsplit_kernel()
{
    __shared__ float ts[64][65];
    const int s0 = blockIdx.x * 64;
    const int bh = blockIdx.y;
    const float* src = g_V + ((size_t)bh * Ss + s0) * Kk;
    const int tid = threadIdx.x;
    #pragma unroll
    for (int it = 0; it < 4; it++){
        int idx = it * 256 + tid;
        int r = idx >> 4;
        int c4 = (idx & 15) << 2;
        float4 v = *(const float4*)&src[(size_t)r * Kk + c4];
        ts[r][c4] = v.x; ts[r][c4+1] = v.y; ts[r][c4+2] = v.z; ts[r][c4+3] = v.w;
    }
    __syncthreads();
    #pragma unroll
    for (int it = 0; it < 2; it++){
        int idx = it * 256 + tid;
        int k = idx >> 3;
        int g8 = (idx & 7) << 3;
        float v[8];
        #pragma unroll
        for (int i = 0; i < 8; i++) v[i] = ts[g8 + i][k];
        uint4 hi, lo; split8(v, hi, lo);
        size_t o = ((size_t)bh * Kk + k) * Ss + s0 + g8;
        *(uint4*)(g_Vthi + o) = hi;
        *(uint4*)(g_Vtlo + o) = lo;
    }
}

// ============================================================================
// Kernel 5: mma probe — does mma.sync bf16 actually compute on this target?
// ones(16x16) x ones(16x8): every C element must be 16.0.
// ============================================================================
__global__ void mma_probe()
{
    const uint32_t one2 = 0x3F803F80u;   // bf16 1.0 packed x2
    uint32_t a[4] = {one2, one2, one2, one2};
    uint32_t b[2] = {one2, one2};
    float c[4] = {0.f, 0.f, 0.f, 0.f};
    mma16816(c, a, b);
    bool ok = (c[0] == 16.0f) && (c[1] == 16.0f) && (c[2] == 16.0f) && (c[3] == 16.0f);
    unsigned m = __ballot_sync(0xffffffffu, ok);
    if ((threadIdx.x & 31) == 0) g_mma_ok = (m == 0xffffffffu) ? 1 : 0;
}

// ============================================================================
// Kernel 6: pv_dual — heads = P @ V.  Branch on g_mma_ok:
//   mma path: bf16 hi/lo split MMA (static 30 KB smem), BK=32, 64 chunks
//   fma path: R5 pv verbatim (aliased into same smem buffer)
// grid (16, BH), 128 threads
// ============================================================================
__global__ __launch_bounds__(128) void pv_dual(const float* __restrict__ probs)
{
    __shared__ __align__(16) char sbuf[SBUF_BYTES];

    const int bh = blockIdx.y;
    const int b = bh / Hh, h = bh % Hh;
    const int s0 = blockIdx.x * 128;
    const int tid = threadIdx.x;

    const float* Pg = probs + ((size_t)bh * Ss + s0) * Ss;

    if (g_mma_ok) {
        // -------------------- MMA path --------------------
        const int lane = tid & 31, w = tid >> 5;   // 4 warps stacked on M
        char* Ah = sbuf;
        char* Al = sbuf + A32SZ;
        char* Bh = sbuf + 2*A32SZ;
        char* Bl = sbuf + 2*A32SZ + B32SZ;

        const __nv_bfloat16* Vh = g_Vthi + (size_t)bh * Kk * Ss;
        const __nv_bfloat16* Vl = g_Vtlo + (size_t)bh * Kk * Ss;

        float acc[2][8][4];
        #pragma unroll
        for (int i = 0; i < 2; i++)
            #pragma unroll
            for (int j = 0; j < 8; j++)
                #pragma unroll
                for (int k = 0; k < 4; k++) acc[i][j][k] = 0.f;

        const int g = lane >> 2, tg = lane & 3;

        for (int c = 0; c < 64; c++){
            const int t0 = c * 32;
            // load P chunk 128x32 fp32 -> split (512 items, 4 iters)
            #pragma unroll
            for (int i = 0; i < 4; i++){
                int idx = i * 128 + tid;
                int row = idx >> 2, gq = idx & 3;
                float v[8];
                const float* src = Pg + (size_t)row * Ss + t0 + gq * 8;
                *(float4*)v       = *(const float4*)src;
                *(float4*)(v + 4) = *(const float4*)(src + 4);
                uint4 hi, lo; split8(v, hi, lo);
                *(uint4*)(Ah + row * RS2 + gq * 16) = hi;
                *(uint4*)(Al + row * RS2 + gq * 16) = lo;
            }
            // load Vt chunk 64 rows x 32 t (256 items, 2 iters)
            #pragma unroll
            for (int i = 0; i < 2; i++){
                int idx = i * 128 + tid;
                int row = idx >> 2, j = idx & 3;
                *(uint4*)(Bh + row * RS2 + j * 16) =
                    *(const uint4*)(Vh + (size_t)row * Ss + t0 + j * 8);
                *(uint4*)(Bl + row * RS2 + j * 16) =
                    *(const uint4*)(Vl + (size_t)row * Ss + t0 + j * 8);
            }
            __syncthreads();
            #pragma unroll
            for (int ks = 0; ks < 2; ks++){
                const int kb = (ks*16 + tg*2) * 2;
                uint32_t ah[2][4], al[2][4];
                frag_a32(ah[0], Ah, w*32 + g,      kb);
                frag_a32(ah[1], Ah, w*32 + 16 + g, kb);
                frag_a32(al[0], Al, w*32 + g,      kb);
                frag_a32(al[1], Al, w*32 + 16 + g, kb);
                #pragma unroll
                for (int nt = 0; nt < 8; nt++){
                    uint32_t bh2[2], bl2[2];
                    frag_b32(bh2, Bh, nt*8 + g, kb);
                    frag_b32(bl2, Bl, nt*8 + g, kb);
                    #pragma unroll
                    for (int mt = 0; mt < 2; mt++){
                        mma16816(acc[mt][nt], ah[mt], bh2);
                        mma16816(acc[mt][nt], ah[mt], bl2);
                        mma16816(acc[mt][nt], al[mt], bh2);
                    }
                }
            }
            __syncthreads();
        }

        #pragma unroll
        for (int mt = 0; mt < 2; mt++)
            #pragma unroll
            for (int nt = 0; nt < 8; nt++){
                const int cc = nt * 8 + tg * 2;
                #pragma unroll
                for (int p = 0; p < 2; p++){
                    const int r = s0 + w * 32 + mt * 16 + g + p * 8;
                    float2 o;
                    o.x = acc[mt][nt][p*2];
                    o.y = acc[mt][nt][p*2+1];
                    *(float2*)&g_heads[((size_t)(b * Ss + r)) * (Hh * Kk) + h * Kk + cc] = o;
                }
            }
    } else {
        // -------------------- FMA path (R5 pv verbatim) --------------------
        float (*Pt)[132] = (float(*)[132])sbuf;              // 32*132*4 = 16896
        float (*Vs)[68]  = (float(*)[68])(sbuf + 16896);     // 32*68*4  =  8704

        const float* Vg = g_V + (size_t)bh * Ss * Kk;

        const int r0 = (tid >> 3) << 3;
        const int c0 = (tid & 7) << 3;

        float acc[8][8];
        #pragma unroll
        for (int i = 0; i < 8; i++)
            #pragma unroll
            for (int j = 0; j < 8; j++) acc[i][j] = 0.f;

        for (int t0 = 0; t0 < Ss; t0 += 32) {
            #pragma unroll
            for (int it = 0; it < 8; it++) {
                const int idx = it * 128 + tid;
                const int row = idx >> 3;
                const int q4  = (idx & 7) << 2;
                const float4 v = *(const float4*)&Pg[(size_t)row * Ss + t0 + q4];
                Pt[q4 + 0][row] = v.x; Pt[q4 + 1][row] = v.y;
                Pt[q4 + 2][row] = v.z; Pt[q4 + 3][row] = v.w;
            }
            #pragma unroll
            for (int it = 0; it < 4; it++) {
                const int idx = it * 128 + tid;
                const int tt = idx >> 4;
                const int c4 = (idx & 15) << 2;
                *(float4*)&Vs[tt][c4] = *(const float4*)&Vg[(size_t)(t0 + tt) * Kk + c4];
            }
            __syncthreads();
            #pragma unroll
            for (int tt = 0; tt < 32; tt++) {
                const float4 a0 = *(const float4*)&Pt[tt][r0];
                const float4 a1 = *(const float4*)&Pt[tt][r0 + 4];
                const float4 b0 = *(const float4*)&Vs[tt][c0];
                const float4 b1 = *(const float4*)&Vs[tt][c0 + 4];
                MICRO_FMA(acc, a0, a1, b0, b1);
            }
            __syncthreads();
        }

        #pragma unroll
        for (int i = 0; i < 8; i++) {
            float* orow = g_heads + ((size_t)(b * Ss + s0 + r0 + i)) * (Hh * Kk) + h * Kk;
            float4 o0, o1;
            o0.x = acc[i][0]; o0.y = acc[i][1]; o0.z = acc[i][2]; o0.w = acc[i][3];
            o1.x = acc[i][4]; o1.y = acc[i][5]; o1.z = acc[i][6]; o1.w = acc[i][7];
            *(float4*)&orow[c0]     = o0;
            *(float4*)&orow[c0 + 4] = o1;
        }
    }
}

// ============================================================================
// Kernel 7 (R5, verbatim): output projection. grid (16, 32), 128 threads
// ============================================================================
__global__ __launch_bounds__(128) void proj_kernel(
    const float* __restrict__ Wp, const float* __restrict__ bp,
    float* __restrict__ out)
{
    __shared__ float At[32][132];
    __shared__ float Bs[32][68];

    const int tid = threadIdx.x;
    const int n0 = blockIdx.x * 64;
    const int m0 = blockIdx.y * 128;
    const int HK = Hh * Kk;   // 1024

    const float* A = g_heads + (size_t)m0 * HK;

    const int r0 = (tid >> 3) << 3;
    const int c0 = (tid & 7) << 3;

    float acc[8][8];
    #pragma unroll
    for (int i = 0; i < 8; i++)
        #pragma unroll
        for (int j = 0; j < 8; j++) acc[i][j] = 0.f;

    for (int d0 = 0; d0 < HK; d0 += 32) {
        #pragma unroll
        for (int it = 0; it < 8; it++) {
            const int idx = it * 128 + tid;
            const int row = idx >> 3;
            const int k4  = (idx & 7) << 2;
            const float4 v = *(const float4*)&A[(size_t)row * HK + d0 + k4];
            At[k4 + 0][row] = v.x; At[k4 + 1][row] = v.y;
            At[k4 + 2][row] = v.z; At[k4 + 3][row] = v.w;
        }
        #pragma unroll
        for (int it = 0; it < 4; it++) {
            const int idx = it * 128 + tid;
            const int dd = idx >> 4;
            const int c4 = (idx & 15) << 2;
            *(float4*)&Bs[dd][c4] = *(const float4*)&Wp[(size_t)(d0 + dd) * Dd + n0 + c4];
        }
        __syncthreads();
        #pragma unroll
        for (int dd = 0; dd < 32; dd++) {
            const float4 a0 = *(const float4*)&At[dd][r0];
            const float4 a1 = *(const float4*)&At[dd][r0 + 4];
            const float4 b0 = *(const float4*)&Bs[dd][c0];
            const float4 b1 = *(const float4*)&Bs[dd][c0 + 4];
            MICRO_FMA(acc, a0, a1, b0, b1);
        }
        __syncthreads();
    }

    float bv[8];
    #pragma unroll
    for (int j = 0; j < 8; j++) bv[j] = bp[n0 + c0 + j];

    #pragma unroll
    for (int i = 0; i < 8; i++) {
        float4 o0, o1;
        o0.x = acc[i][0] + bv[0]; o0.y = acc[i][1] + bv[1];
        o0.z = acc[i][2] + bv[2]; o0.w = acc[i][3] + bv[3];
        o1.x = acc[i][4] + bv[4]; o1.y = acc[i][5] + bv[5];
        o1.z = acc[i][6] + bv[6]; o1.w = acc[i][7] + bv[7];
        *(float4*)&out[(size_t)(m0 + r0 + i) * Dd + n0 + c0]     = o0;
        *(float4*)&out[(size_t)(m0 + r0 + i) * Dd + n0 + c0 + 4] = o1;
    }
}

// ============================================================================
extern "C" void kernel_launch(void* const* d_in, const int* in_sizes, int n_in,
                              void* d_out, int out_size)
{
    const float* x      = (const float*)d_in[0];
    const float* W_Q    = (const float*)d_in[1];
    const float* b_Q    = (const float*)d_in[2];
    const float* W_K    = (const float*)d_in[3];
    const float* b_K    = (const float*)d_in[4];
    const float* W_V    = (const float*)d_in[5];
    const float* b_V    = (const float*)d_in[6];
    const float* W_proj = (const float*)d_in[7];
    const float* b_proj = (const float*)d_in[8];
    const int*   amask  = (const int*)d_in[9];

    float* out        = (float*)d_out;                  // [B,S,D]
    float* out_scores = out + (size_t)Bb * Ss * Dd;     // [B,H,S,S]

    // 0) probe whether mma.sync bf16 actually computes on this target
    mma_probe<<<1, 32>>>();

    // 1) QKV projections
    qkv_kernel<<<dim3(16, BH, 3), 128>>>(x, W_Q, b_Q, W_K, b_K, W_V, b_V);

    // 2) masked scaled scores -> out_scores
    {
        const int smem = 2 * 64 * 132 * (int)sizeof(float);   // 67.6 KB (proven)
        cudaFuncSetAttribute(scores_kernel, cudaFuncAttributeMaxDynamicSharedMemorySize, smem);
        scores_kernel<<<dim3(Hh, 256, Bb), 256, smem>>>(amask, out_scores);
    }

    // 3) in-place softmax (normalized P = output 1)
    softmax_kernel<<<BH * Ss, 256>>>(out_scores);

    // 3b) V transpose + split (for the mma path)
    vsplit_kernel<<<dim3(Ss / 64, BH), 256>>>();

    // 4) P @ V — dual path selected by probe result
    pv_dual<<<dim3(16, BH), 128>>>(out_scores);

    // 5) output projection
    proj_kernel<<<dim3(16, (Bb * Ss) / 128), 128>>>(W_proj, b_proj, out);
}

// round 15
// speedup vs baseline: 1.6483x; 1.1109x over previous
#include <cuda_runtime.h>
#include <cuda_bf16.h>
#include <cstdint>

// Problem constants
#define Bb 2
#define Ss 2048
#define Dd 1024
#define Hh 16
#define Kk 64
#define BH (Bb*Hh)          // 32
#define SCALE 0.125f
#define NEGF  (-3.402823466e38f)

// ---------------- scratch (static device globals) ----------------
#define QKSZ ((size_t)BH*Ss*Kk)   // 4,194,304

__device__ float g_Q[QKSZ];                          // [bh][s][k]
__device__ float g_K[QKSZ];
__device__ float g_V[QKSZ];
__device__ float g_heads[(size_t)Bb*Ss*Hh*Kk];       // [b][s][hk]
__device__ __nv_bfloat16 g_Vthi[QKSZ], g_Vtlo[QKSZ]; // V^T split [bh][k][s]
__device__ __nv_bfloat16 g_Qhi[QKSZ],  g_Qlo[QKSZ];  // Q split [bh][s][k]
__device__ __nv_bfloat16 g_Khi[QKSZ],  g_Klo[QKSZ];  // K split [bh][s][k]
__device__ int g_mma_ok;                             // probe result

// ============================ helpers =======================================
__device__ __forceinline__ uint32_t pk2(float lo_, float hi_){
    uint32_t r;
    asm("cvt.rn.bf16x2.f32 %0, %1, %2;" : "=r"(r) : "f"(hi_), "f"(lo_));
    return r;
}
__device__ __forceinline__ void split8(const float* v, uint4& hi, uint4& lo){
    float h[8];
    #pragma unroll
    for (int i = 0; i < 8; i++) h[i] = __bfloat162float(__float2bfloat16_rn(v[i]));
    hi.x = pk2(h[0], h[1]); hi.y = pk2(h[2], h[3]);
    hi.z = pk2(h[4], h[5]); hi.w = pk2(h[6], h[7]);
    lo.x = pk2(v[0]-h[0], v[1]-h[1]); lo.y = pk2(v[2]-h[2], v[3]-h[3]);
    lo.z = pk2(v[4]-h[4], v[5]-h[5]); lo.w = pk2(v[6]-h[6], v[7]-h[7]);
}
__device__ __forceinline__ void mma16816(float* c, const uint32_t a[4], const uint32_t b[2]){
    asm volatile("mma.sync.aligned.m16n8k16.row.col.f32.bf16.bf16.f32 "
        "{%0,%1,%2,%3}, {%4,%5,%6,%7}, {%8,%9}, {%0,%1,%2,%3};"
        : "+f"(c[0]), "+f"(c[1]), "+f"(c[2]), "+f"(c[3])
        : "r"(a[0]), "r"(a[1]), "r"(a[2]), "r"(a[3]), "r"(b[0]), "r"(b[1]));
}

// 64-FMA micro-kernel helper
#define MICRO_FMA(acc, a0, a1, b0, b1)                                   \
    {                                                                    \
        float _a[8] = {a0.x, a0.y, a0.z, a0.w, a1.x, a1.y, a1.z, a1.w};  \
        float _b[8] = {b0.x, b0.y, b0.z, b0.w, b1.x, b1.y, b1.z, b1.w};  \
        _Pragma("unroll")                                                \
        for (int _i = 0; _i < 8; _i++) {                                 \
            _Pragma("unroll")                                            \
            for (int _j = 0; _j < 8; _j++)                               \
                acc[_i][_j] += _a[_i] * _b[_j];                          \
        }                                                                \
    }

// mma-path smem geometry: rows padded to 80 B -> conflict-free word idx 20r+tg
#define RS2    80
#define A32SZ  (128*RS2)    // 10240
#define B32SZ  (64*RS2)     // 5120
#define SBUF_BYTES (2*A32SZ + 2*B32SZ)   // 30720

__device__ __forceinline__ void frag_a32(uint32_t (&a)[4], const char* base, int row, int kb){
    a[0] = *(const uint32_t*)(base + (size_t)row       * RS2 + kb);
    a[1] = *(const uint32_t*)(base + (size_t)(row + 8) * RS2 + kb);
    a[2] = *(const uint32_t*)(base + (size_t)row       * RS2 + kb + 16);
    a[3] = *(const uint32_t*)(base + (size_t)(row + 8) * RS2 + kb + 16);
}
__device__ __forceinline__ void frag_b32(uint32_t (&b)[2], const char* base, int row, int kb){
    b[0] = *(const uint32_t*)(base + (size_t)row * RS2 + kb);
    b[1] = *(const uint32_t*)(base + (size_t)row * RS2 + kb + 16);
}

// ============================================================================
// Kernel 1 (R5, verbatim): QKV projection. grid (16, BH, 3), 128 threads
// ============================================================================
__global__ __launch_bounds__(128) void qkv_kernel(
    const float* __restrict__ x,
    const float* __restrict__ W_Q, const float* __restrict__ b_Q,
    const float* __restrict__ W_K, const float* __restrict__ b_K,
    const float* __restrict__ W_V, const float* __restrict__ b_V)
{
    const int stile = blockIdx.x;
    const int bh    = blockIdx.y;
    const int which = blockIdx.z;
    const int b = bh / Hh, h = bh % Hh;

    const float* W    = (which == 0) ? W_Q : (which == 1) ? W_K : W_V;
    const float* bias = (which == 0) ? b_Q : (which == 1) ? b_K : b_V;
    float*       out  = (which == 0) ? g_Q : (which == 1) ? g_K : g_V;

    __shared__ float At[32][132];
    __shared__ float Bs[32][68];

    const int tid = threadIdx.x;
    const int s0 = stile * 128;
    const float* Ax = x + ((size_t)b * Ss + s0) * Dd;
    const float* Wh = W + (size_t)h * Dd * Kk;

    const int r0 = (tid >> 3) << 3;
    const int c0 = (tid & 7) << 3;

    float acc[8][8];
    #pragma unroll
    for (int i = 0; i < 8; i++)
        #pragma unroll
        for (int j = 0; j < 8; j++) acc[i][j] = 0.f;

    for (int d0 = 0; d0 < Dd; d0 += 32) {
        #pragma unroll
        for (int it = 0; it < 8; it++) {
            const int idx = it * 128 + tid;
            const int row = idx >> 3;
            const int k4  = (idx & 7) << 2;
            const float4 v = *(const float4*)&Ax[(size_t)row * Dd + d0 + k4];
            At[k4 + 0][row] = v.x; At[k4 + 1][row] = v.y;
            At[k4 + 2][row] = v.z; At[k4 + 3][row] = v.w;
        }
        #pragma unroll
        for (int it = 0; it < 4; it++) {
            const int idx = it * 128 + tid;
            const int dd = idx >> 4;
            const int c4 = (idx & 15) << 2;
            *(float4*)&Bs[dd][c4] = *(const float4*)&Wh[(size_t)(d0 + dd) * Kk + c4];
        }
        __syncthreads();
        #pragma unroll
        for (int dd = 0; dd < 32; dd++) {
            const float4 a0 = *(const float4*)&At[dd][r0];
            const float4 a1 = *(const float4*)&At[dd][r0 + 4];
            const float4 b0 = *(const float4*)&Bs[dd][c0];
            const float4 b1 = *(const float4*)&Bs[dd][c0 + 4];
            MICRO_FMA(acc, a0, a1, b0, b1);
        }
        __syncthreads();
    }

    float bv[8];
    #pragma unroll
    for (int j = 0; j < 8; j++) bv[j] = bias[h * Kk + c0 + j];

    float* outp = out + ((size_t)bh * Ss + s0) * Kk;
    #pragma unroll
    for (int i = 0; i < 8; i++) {
        float4 o0, o1;
        o0.x = acc[i][0] + bv[0]; o0.y = acc[i][1] + bv[1];
        o0.z = acc[i][2] + bv[2]; o0.w = acc[i][3] + bv[3];
        o1.x = acc[i][4] + bv[4]; o1.y = acc[i][5] + bv[5];
        o1.z = acc[i][6] + bv[6]; o1.w = acc[i][7] + bv[7];
        *(float4*)&outp[(size_t)(r0 + i) * Kk + c0]     = o0;
        *(float4*)&outp[(size_t)(r0 + i) * Kk + c0 + 4] = o1;
    }
}

// ============================================================================
// Kernel 1b: qksplit — elementwise bf16 hi/lo split of g_Q and g_K.
// grid (QKSZ/(256*8), 2): y=0 -> Q, y=1 -> K.  256 threads.
// ============================================================================
__global__ __launch_bounds__(256) void qksplit_kernel()
{
    const size_t i = ((size_t)blockIdx.x * 256 + threadIdx.x) * 8;
    const float* src = (blockIdx.y == 0) ? g_Q : g_K;
    __nv_bfloat16* dhi = (blockIdx.y == 0) ? g_Qhi : g_Khi;
    __nv_bfloat16* dlo = (blockIdx.y == 0) ? g_Qlo : g_Klo;
    float v[8];
    *(float4*)v     = *(const float4*)(src + i);
    *(float4*)(v+4) = *(const float4*)(src + i + 4);
    uint4 hi, lo; split8(v, hi, lo);
    *(uint4*)(dhi + i) = hi;
    *(uint4*)(dlo + i) = lo;
}

// ============================================================================
// Kernel 2a: scores via MMA (runs iff g_mma_ok).
// D[s,t] = mask(Q·K^T * scale).  BM=128, BN=64, red=64 (2 chunks of 32).
// 128 threads, 4 warps stacked on M (pv_dual-proven layout).
// grid (Ss/64=32 ttile, 16 stile, BH)
// ============================================================================
__global__ __launch_bounds__(128) void scores_mma(
    const int* __restrict__ mask, float* __restrict__ out_scores)
{
    if (!g_mma_ok) return;
    __shared__ __align__(16) char sbuf[SBUF_BYTES];

    const int tid = threadIdx.x, lane = tid & 31, w = tid >> 5;
    const int t0 = blockIdx.x * 64;
    const int s0 = blockIdx.y * 128;
    const int bh = blockIdx.z;
    const int b  = bh >> 4;

    char* Ah = sbuf;
    char* Al = sbuf + A32SZ;
    char* Bh = sbuf + 2*A32SZ;
    char* Bl = sbuf + 2*A32SZ + B32SZ;

    const __nv_bfloat16* Qh = g_Qhi + (size_t)(bh * Ss + s0) * Kk;
    const __nv_bfloat16* Ql = g_Qlo + (size_t)(bh * Ss + s0) * Kk;
    const __nv_bfloat16* Kh = g_Khi + (size_t)(bh * Ss + t0) * Kk;
    const __nv_bfloat16* Kl = g_Klo + (size_t)(bh * Ss + t0) * Kk;

    float acc[2][8][4];
    #pragma unroll
    for (int i = 0; i < 2; i++)
        #pragma unroll
        for (int j = 0; j < 8; j++)
            #pragma unroll
            for (int k = 0; k < 4; k++) acc[i][j][k] = 0.f;

    const int g = lane >> 2, tg = lane & 3;

    #pragma unroll
    for (int c = 0; c < 2; c++){
        const int k0 = c * 32;
        // A: Q chunk 128 rows x 32 k, hi/lo (512 uint4 items, 4 iters)
        #pragma unroll
        for (int i = 0; i < 4; i++){
            int idx = i * 128 + tid;
            int row = idx >> 2, j = idx & 3;
            *(uint4*)(Ah + row * RS2 + j * 16) =
                *(const uint4*)(Qh + (size_t)row * Kk + k0 + j * 8);
            *(uint4*)(Al + row * RS2 + j * 16) =
                *(const uint4*)(Ql + (size_t)row * Kk + k0 + j * 8);
        }
        // B: K chunk 64 rows x 32 k, hi/lo (256 items, 2 iters)
        #pragma unroll
        for (int i = 0; i < 2; i++){
            int idx = i * 128 + tid;
            int row = idx >> 2, j = idx & 3;
            *(uint4*)(Bh + row * RS2 + j * 16) =
                *(const uint4*)(Kh + (size_t)row * Kk + k0 + j * 8);
            *(uint4*)(Bl + row * RS2 + j * 16) =
                *(const uint4*)(Kl + (size_t)row * Kk + k0 + j * 8);
        }
        __syncthreads();
        #pragma unroll
        for (int ks = 0; ks < 2; ks++){
            const int kb = (ks*16 + tg*2) * 2;
            uint32_t ah[2][4], al[2][4];
            frag_a32(ah[0], Ah, w*32 + g,      kb);
            frag_a32(ah[1], Ah, w*32 + 16 + g, kb);
            frag_a32(al[0], Al, w*32 + g,      kb);
            frag_a32(al[1], Al, w*32 + 16 + g, kb);
            #pragma unroll
            for (int nt = 0; nt < 8; nt++){
                uint32_t bh2[2], bl2[2];
                frag_b32(bh2, Bh, nt*8 + g, kb);
                frag_b32(bl2, Bl, nt*8 + g, kb);
                #pragma unroll
                for (int mt = 0; mt < 2; mt++){
                    mma16816(acc[mt][nt], ah[mt], bh2);
                    mma16816(acc[mt][nt], ah[mt], bl2);
                    mma16816(acc[mt][nt], al[mt], bh2);
                }
            }
        }
        __syncthreads();
    }

    // epilogue: mask + scale + store
    #pragma unroll
    for (int mt = 0; mt < 2; mt++)
        #pragma unroll
        for (int p = 0; p < 2; p++){
            const int r = s0 + w * 32 + mt * 16 + g + p * 8;
            const int* mrow = mask + ((size_t)b * Ss + r) * Ss + t0;
            float* orow = out_scores + ((size_t)bh * Ss + r) * Ss + t0;
            #pragma unroll
            for (int nt = 0; nt < 8; nt++){
                const int cc = nt * 8 + tg * 2;
                const int2 m = *(const int2*)(mrow + cc);
                float2 o;
                o.x = m.x ? acc[mt][nt][p*2]   * SCALE : NEGF;
                o.y = m.y ? acc[mt][nt][p*2+1] * SCALE : NEGF;
                *(float2*)(orow + cc) = o;
            }
        }
}

// ============================================================================
// Kernel 2b (R5, verbatim + early-exit): fp32 scores fallback (runs iff !ok)
// ============================================================================
__global__ __launch_bounds__(256) void scores_kernel(
    const int* __restrict__ mask, float* __restrict__ out_scores)
{
    if (g_mma_ok) return;
    extern __shared__ float sm[];
    float (*Qt)[132] = (float(*)[132])sm;
    float (*Kt)[132] = (float(*)[132])(sm + 64 * 132);

    const int h  = blockIdx.x;
    const int b  = blockIdx.z;
    const int bh = b * Hh + h;
    const int st = blockIdx.y & 15;
    const int tt = blockIdx.y >> 4;
    const int s0 = st * 128;
    const int t0 = tt * 128;
    const int tid = threadIdx.x;

    const float* Qg = g_Q + ((size_t)bh * Ss + s0) * Kk;
    const float* Kg = g_K + ((size_t)bh * Ss + t0) * Kk;

    #pragma unroll
    for (int it = 0; it < 8; it++) {
        const int idx = it * 256 + tid;
        const int row = idx >> 4;
        const int k4  = (idx & 15) << 2;
        const float4 q = *(const float4*)&Qg[(size_t)row * Kk + k4];
        Qt[k4 + 0][row] = q.x; Qt[k4 + 1][row] = q.y;
        Qt[k4 + 2][row] = q.z; Qt[k4 + 3][row] = q.w;
        const float4 k = *(const float4*)&Kg[(size_t)row * Kk + k4];
        Kt[k4 + 0][row] = k.x; Kt[k4 + 1][row] = k.y;
        Kt[k4 + 2][row] = k.z; Kt[k4 + 3][row] = k.w;
    }
    __syncthreads();

    const int r0 = (tid >> 4) << 3;
    const int c0 = (tid & 15) << 3;

    float acc[8][8];
    #pragma unroll
    for (int i = 0; i < 8; i++)
        #pragma unroll
        for (int j = 0; j < 8; j++) acc[i][j] = 0.f;

    #pragma unroll 8
    for (int k = 0; k < Kk; k++) {
        const float4 a0 = *(const float4*)&Qt[k][r0];
        const float4 a1 = *(const float4*)&Qt[k][r0 + 4];
        const float4 b0 = *(const float4*)&Kt[k][c0];
        const float4 b1 = *(const float4*)&Kt[k][c0 + 4];
        MICRO_FMA(acc, a0, a1, b0, b1);
    }

    #pragma unroll
    for (int i = 0; i < 8; i++) {
        const int s = s0 + r0 + i;
        const int* mrow = mask + ((size_t)b * Ss + s) * Ss + t0;
        const int4 m0 = *(const int4*)&mrow[c0];
        const int4 m1 = *(const int4*)&mrow[c0 + 4];
        float4 o0, o1;
        o0.x = m0.x ? acc[i][0] * SCALE : NEGF;
        o0.y = m0.y ? acc[i][1] * SCALE : NEGF;
        o0.z = m0.z ? acc[i][2] * SCALE : NEGF;
        o0.w = m0.w ? acc[i][3] * SCALE : NEGF;
        o1.x = m1.x ? acc[i][4] * SCALE : NEGF;
        o1.y = m1.y ? acc[i][5] * SCALE : NEGF;
        o1.z = m1.z ? acc[i][6] * SCALE : NEGF;
        o1.w = m1.w ? acc[i][7] * SCALE : NEGF;
        float* orow = out_scores + ((size_t)bh * Ss + s) * Ss + t0;
        *(float4*)&orow[c0]     = o0;
        *(float4*)&orow[c0 + 4] = o1;
    }
}

// ============================================================================
// Kernel 3 (R5, verbatim): in-place row softmax. grid (BH*S), 256 threads
// ============================================================================
__global__ __launch_bounds__(256) void softmax_kernel(float* __restrict__ scores)
{
    __shared__ float red[8];
    __shared__ float bcast;

    float4* row = (float4*)(scores + (size_t)blockIdx.x * Ss);
    const int tid = threadIdx.x;
    const int lane = tid & 31, warp = tid >> 5;

    float4 v0 = row[tid];
    float4 v1 = row[tid + 256];

    float mx = fmaxf(fmaxf(fmaxf(v0.x, v0.y), fmaxf(v0.z, v0.w)),
                     fmaxf(fmaxf(v1.x, v1.y), fmaxf(v1.z, v1.w)));
    #pragma unroll
    for (int o = 16; o > 0; o >>= 1) mx = fmaxf(mx, __shfl_xor_sync(0xffffffffu, mx, o));
    if (lane == 0) red[warp] = mx;
    __syncthreads();
    if (tid == 0) {
        float m = red[0];
        #pragma unroll
        for (int i = 1; i < 8; i++) m = fmaxf(m, red[i]);
        bcast = m;
    }
    __syncthreads();
    mx = bcast;

    v0.x = __expf(v0.x - mx); v0.y = __expf(v0.y - mx);
    v0.z = __expf(v0.z - mx); v0.w = __expf(v0.w - mx);
    v1.x = __expf(v1.x - mx); v1.y = __expf(v1.y - mx);
    v1.z = __expf(v1.z - mx); v1.w = __expf(v1.w - mx);
    float sum = v0.x + v0.y + v0.z + v0.w + v1.x + v1.y + v1.z + v1.w;
    #pragma unroll
    for (int o = 16; o > 0; o >>= 1) sum += __shfl_xor_sync(0xffffffffu, sum, o);
    __syncthreads();
    if (lane == 0) red[warp] = sum;
    __syncthreads();
    if (tid == 0) {
        float s = 0.f;
        #pragma unroll
        for (int i = 0; i < 8; i++) s += red[i];
        bcast = 1.0f / s;
    }
    __syncthreads();
    const float inv = bcast;

    v0.x *= inv; v0.y *= inv; v0.z *= inv; v0.w *= inv;
    v1.x *= inv; v1.y *= inv; v1.z *= inv; v1.w *= inv;
    row[tid]       = v0;
    row[tid + 256] = v1;
}

// ============================================================================
// Kernel 4: vsplit — transpose+split g_V fp32 -> Vt hi/lo [bh][k][s]
// grid (32, BH), 256 threads
// ============================================================================
__global__ __launch_bounds__(256) void vsplit_kernel()
{
    __shared__ float ts[64][65];
    const int s0 = blockIdx.x * 64;
    const int bh = blockIdx.y;
    const float* src = g_V + ((size_t)bh * Ss + s0) * Kk;
    const int tid = threadIdx.x;
    #pragma unroll
    for (int it = 0; it < 4; it++){
        int idx = it * 256 + tid;
        int r = idx >> 4;
        int c4 = (idx & 15) << 2;
        float4 v = *(const float4*)&src[(size_t)r * Kk + c4];
        ts[r][c4] = v.x; ts[r][c4+1] = v.y; ts[r][c4+2] = v.z; ts[r][c4+3] = v.w;
    }
    __syncthreads();
    #pragma unroll
    for (int it = 0; it < 2; it++){
        int idx = it * 256 + tid;
        int k = idx >> 3;
        int g8 = (idx & 7) << 3;
        float v[8];
        #pragma unroll
        for (int i = 0; i < 8; i++) v[i] = ts[g8 + i][k];
        uint4 hi, lo; split8(v, hi, lo);
        size_t o = ((size_t)bh * Kk + k) * Ss + s0 + g8;
        *(uint4*)(g_Vthi + o) = hi;
        *(uint4*)(g_Vtlo + o) = lo;
    }
}

// ============================================================================
// Kernel 5: mma probe
// ============================================================================
__global__ void mma_probe()
{
    const uint32_t one2 = 0x3F803F80u;   // bf16 1.0 packed x2
    uint32_t a[4] = {one2, one2, one2, one2};
    uint32_t b[2] = {one2, one2};
    float c[4] = {0.f, 0.f, 0.f, 0.f};
    mma16816(c, a, b);
    bool ok = (c[0] == 16.0f) && (c[1] == 16.0f) && (c[2] == 16.0f) && (c[3] == 16.0f);
    unsigned m = __ballot_sync(0xffffffffu, ok);
    if ((threadIdx.x & 31) == 0) g_mma_ok = (m == 0xffffffffu) ? 1 : 0;
}

// ============================================================================
// Kernel 6 (R14, verbatim): pv_dual — heads = P @ V, probe-selected path.
// grid (16, BH), 128 threads
// ============================================================================
__global__ __launch_bounds__(128) void pv_dual(const float* __restrict__ probs)
{
    __shared__ __align__(16) char sbuf[SBUF_BYTES];

    const int bh = blockIdx.y;
    const int b = bh / Hh, h = bh % Hh;
    const int s0 = blockIdx.x * 128;
    const int tid = threadIdx.x;

    const float* Pg = probs + ((size_t)bh * Ss + s0) * Ss;

    if (g_mma_ok) {
        const int lane = tid & 31, w = tid >> 5;
        char* Ah = sbuf;
        char* Al = sbuf + A32SZ;
        char* Bh = sbuf + 2*A32SZ;
        char* Bl = sbuf + 2*A32SZ + B32SZ;

        const __nv_bfloat16* Vh = g_Vthi + (size_t)bh * Kk * Ss;
        const __nv_bfloat16* Vl = g_Vtlo + (size_t)bh * Kk * Ss;

        float acc[2][8][4];
        #pragma unroll
        for (int i = 0; i < 2; i++)
            #pragma unroll
            for (int j = 0; j < 8; j++)
                #pragma unroll
                for (int k = 0; k < 4; k++) acc[i][j][k] = 0.f;

        const int g = lane >> 2, tg = lane & 3;

        for (int c = 0; c < 64; c++){
            const int t0 = c * 32;
            #pragma unroll
            for (int i = 0; i < 4; i++){
                int idx = i * 128 + tid;
                int row = idx >> 2, gq = idx & 3;
                float v[8];
                const float* src = Pg + (size_t)row * Ss + t0 + gq * 8;
                *(float4*)v       = *(const float4*)src;
                *(float4*)(v + 4) = *(const float4*)(src + 4);
                uint4 hi, lo; split8(v, hi, lo);
                *(uint4*)(Ah + row * RS2 + gq * 16) = hi;
                *(uint4*)(Al + row * RS2 + gq * 16) = lo;
            }
            #pragma unroll
            for (int i = 0; i < 2; i++){
                int idx = i * 128 + tid;
                int row = idx >> 2, j = idx & 3;
                *(uint4*)(Bh + row * RS2 + j * 16) =
                    *(const uint4*)(Vh + (size_t)row * Ss + t0 + j * 8);
                *(uint4*)(Bl + row * RS2 + j * 16) =
                    *(const uint4*)(Vl + (size_t)row * Ss + t0 + j * 8);
            }
            __syncthreads();
            #pragma unroll
            for (int ks = 0; ks < 2; ks++){
                const int kb = (ks*16 + tg*2) * 2;
                uint32_t ah[2][4], al[2][4];
                frag_a32(ah[0], Ah, w*32 + g,      kb);
                frag_a32(ah[1], Ah, w*32 + 16 + g, kb);
                frag_a32(al[0], Al, w*32 + g,      kb);
                frag_a32(al[1], Al, w*32 + 16 + g, kb);
                #pragma unroll
                for (int nt = 0; nt < 8; nt++){
                    uint32_t bh2[2], bl2[2];
                    frag_b32(bh2, Bh, nt*8 + g, kb);
                    frag_b32(bl2, Bl, nt*8 + g, kb);
                    #pragma unroll
                    for (int mt = 0; mt < 2; mt++){
                        mma16816(acc[mt][nt], ah[mt], bh2);
                        mma16816(acc[mt][nt], ah[mt], bl2);
                        mma16816(acc[mt][nt], al[mt], bh2);
                    }
                }
            }
            __syncthreads();
        }

        #pragma unroll
        for (int mt = 0; mt < 2; mt++)
            #pragma unroll
            for (int nt = 0; nt < 8; nt++){
                const int cc = nt * 8 + tg * 2;
                #pragma unroll
                for (int p = 0; p < 2; p++){
                    const int r = s0 + w * 32 + mt * 16 + g + p * 8;
                    float2 o;
                    o.x = acc[mt][nt][p*2];
                    o.y = acc[mt][nt][p*2+1];
                    *(float2*)&g_heads[((size_t)(b * Ss + r)) * (Hh * Kk) + h * Kk + cc] = o;
                }
            }
    } else {
        float (*Pt)[132] = (float(*)[132])sbuf;
        float (*Vs)[68]  = (float(*)[68])(sbuf + 16896);

        const float* Vg = g_V + (size_t)bh * Ss * Kk;

        const int r0 = (tid >> 3) << 3;
        const int c0 = (tid & 7) << 3;

        float acc[8][8];
        #pragma unroll
        for (int i = 0; i < 8; i++)
            #pragma unroll
            for (int j = 0; j < 8; j++) acc[i][j] = 0.f;

        for (int t0 = 0; t0 < Ss; t0 += 32) {
            #pragma unroll
            for (int it = 0; it < 8; it++) {
                const int idx = it * 128 + tid;
                const int row = idx >> 3;
                const int q4  = (idx & 7) << 2;
                const float4 v = *(const float4*)&Pg[(size_t)row * Ss + t0 + q4];
                Pt[q4 + 0][row] = v.x; Pt[q4 + 1][row] = v.y;
                Pt[q4 + 2][row] = v.z; Pt[q4 + 3][row] = v.w;
            }
            #pragma unroll
            for (int it = 0; it < 4; it++) {
                const int idx = it * 128 + tid;
                const int tt = idx >> 4;
                const int c4 = (idx & 15) << 2;
                *(float4*)&Vs[tt][c4] = *(const float4*)&Vg[(size_t)(t0 + tt) * Kk + c4];
            }
            __syncthreads();
            #pragma unroll
            for (int tt = 0; tt < 32; tt++) {
                const float4 a0 = *(const float4*)&Pt[tt][r0];
                const float4 a1 = *(const float4*)&Pt[tt][r0 + 4];
                const float4 b0 = *(const float4*)&Vs[tt][c0];
                const float4 b1 = *(const float4*)&Vs[tt][c0 + 4];
                MICRO_FMA(acc, a0, a1, b0, b1);
            }
            __syncthreads();
        }

        #pragma unroll
        for (int i = 0; i < 8; i++) {
            float* orow = g_heads + ((size_t)(b * Ss + s0 + r0 + i)) * (Hh * Kk) + h * Kk;
            float4 o0, o1;
            o0.x = acc[i][0]; o0.y = acc[i][1]; o0.z = acc[i][2]; o0.w = acc[i][3];
            o1.x = acc[i][4]; o1.y = acc[i][5]; o1.z = acc[i][6]; o1.w = acc[i][7];
            *(float4*)&orow[c0]     = o0;
            *(float4*)&orow[c0 + 4] = o1;
        }
    }
}

// ============================================================================
// Kernel 7 (R5, verbatim): output projection. grid (16, 32), 128 threads
// ============================================================================
__global__ __launch_bounds__(128) void proj_kernel(
    const float* __restrict__ Wp, const float* __restrict__ bp,
    float* __restrict__ out)
{
    __shared__ float At[32][132];
    __shared__ float Bs[32][68];

    const int tid = threadIdx.x;
    const int n0 = blockIdx.x * 64;
    const int m0 = blockIdx.y * 128;
    const int HK = Hh * Kk;   // 1024

    const float* A = g_heads + (size_t)m0 * HK;

    const int r0 = (tid >> 3) << 3;
    const int c0 = (tid & 7) << 3;

    float acc[8][8];
    #pragma unroll
    for (int i = 0; i < 8; i++)
        #pragma unroll
        for (int j = 0; j < 8; j++) acc[i][j] = 0.f;

    for (int d0 = 0; d0 < HK; d0 += 32) {
        #pragma unroll
        for (int it = 0; it < 8; it++) {
            const int idx = it * 128 + tid;
            const int row = idx >> 3;
            const int k4  = (idx & 7) << 2;
            const float4 v = *(const float4*)&A[(size_t)row * HK + d0 + k4];
            At[k4 + 0][row] = v.x; At[k4 + 1][row] = v.y;
            At[k4 + 2][row] = v.z; At[k4 + 3][row] = v.w;
        }
        #pragma unroll
        for (int it = 0; it < 4; it++) {
            const int idx = it * 128 + tid;
            const int dd = idx >> 4;
            const int c4 = (idx & 15) << 2;
            *(float4*)&Bs[dd][c4] = *(const float4*)&Wp[(size_t)(d0 + dd) * Dd + n0 + c4];
        }
        __syncthreads();
        #pragma unroll
        for (int dd = 0; dd < 32; dd++) {
            const float4 a0 = *(const float4*)&At[dd][r0];
            const float4 a1 = *(const float4*)&At[dd][r0 + 4];
            const float4 b0 = *(const float4*)&Bs[dd][c0];
            const float4 b1 = *(const float4*)&Bs[dd][c0 + 4];
            MICRO_FMA(acc, a0, a1, b0, b1);
        }
        __syncthreads();
    }

    float bv[8];
    #pragma unroll
    for (int j = 0; j < 8; j++) bv[j] = bp[n0 + c0 + j];

    #pragma unroll
    for (int i = 0; i < 8; i++) {
        float4 o0, o1;
        o0.x = acc[i][0] + bv[0]; o0.y = acc[i][1] + bv[1];
        o0.z = acc[i][2] + bv[2]; o0.w = acc[i][3] + bv[3];
        o1.x = acc[i][4] + bv[4]; o1.y = acc[i][5] + bv[5];
        o1.z = acc[i][6] + bv[6]; o1.w = acc[i][7] + bv[7];
        *(float4*)&out[(size_t)(m0 + r0 + i) * Dd + n0 + c0]     = o0;
        *(float4*)&out[(size_t)(m0 + r0 + i) * Dd + n0 + c0 + 4] = o1;
    }
}

// ============================================================================
extern "C" void kernel_launch(void* const* d_in, const int* in_sizes, int n_in,
                              void* d_out, int out_size)
{
    const float* x      = (const float*)d_in[0];
    const float* W_Q    = (const float*)d_in[1];
    const float* b_Q    = (const float*)d_in[2];
    const float* W_K    = (const float*)d_in[3];
    const float* b_K    = (const float*)d_in[4];
    const float* W_V    = (const float*)d_in[5];
    const float* b_V    = (const float*)d_in[6];
    const float* W_proj = (const float*)d_in[7];
    const float* b_proj = (const float*)d_in[8];
    const int*   amask  = (const int*)d_in[9];

    float* out        = (float*)d_out;                  // [B,S,D]
    float* out_scores = out + (size_t)Bb * Ss * Dd;     // [B,H,S,S]

    // 0) probe mma.sync
    mma_probe<<<1, 32>>>();

    // 1) QKV projections (fp32)
    qkv_kernel<<<dim3(16, BH, 3), 128>>>(x, W_Q, b_Q, W_K, b_K, W_V, b_V);

    // 1b) split Q/K into bf16 hi/lo (for mma scores)
    qksplit_kernel<<<dim3((int)(QKSZ / (256 * 8)), 2), 256>>>();

    // 2) masked scaled scores — dual path (exactly one does work)
    scores_mma<<<dim3(Ss / 64, 16, BH), 128>>>(amask, out_scores);
    {
        const int smem = 2 * 64 * 132 * (int)sizeof(float);
        cudaFuncSetAttribute(scores_kernel, cudaFuncAttributeMaxDynamicSharedMemorySize, smem);
        scores_kernel<<<dim3(Hh, 256, Bb), 256, smem>>>(amask, out_scores);
    }

    // 3) in-place softmax (normalized P = output 1)
    softmax_kernel<<<BH * Ss, 256>>>(out_scores);

    // 3b) V transpose + split
    vsplit_kernel<<<dim3(Ss / 64, BH), 256>>>();

    // 4) P @ V — dual path
    pv_dual<<<dim3(16, BH), 128>>>(out_scores);

    // 5) output projection
    proj_kernel<<<dim3(16, (Bb * Ss) / 128), 128>>>(W_proj, b_proj, out);
}

// round 17
// speedup vs baseline: 2.3178x; 1.4061x over previous
#include <cuda_runtime.h>
#include <cuda_bf16.h>
#include <cstdint>

// Problem constants
#define Bb 2
#define Ss 2048
#define Dd 1024
#define Hh 16
#define Kk 64
#define BH (Bb*Hh)          // 32
#define SCALE 0.125f
#define NEGF  (-3.402823466e38f)

// ---------------- scratch (static device globals) ----------------
#define QKSZ ((size_t)BH*Ss*Kk)        // 4,194,304
#define XSZ  ((size_t)Bb*Ss*Dd)        // 4,194,304
#define WSZ  ((size_t)3*Hh*Kk*Dd)      // 3,145,728
#define WPSZ ((size_t)Dd*Dd)           // 1,048,576

__device__ float g_Q[QKSZ];                          // [bh][s][k]
__device__ float g_K[QKSZ];
__device__ float g_V[QKSZ];
__device__ float g_heads[(size_t)Bb*Ss*Hh*Kk];       // [b][s][hk] (fallback)
__device__ __nv_bfloat16 g_Vthi[QKSZ], g_Vtlo[QKSZ]; // V^T split [bh][k][s]
__device__ __nv_bfloat16 g_Qhi[QKSZ],  g_Qlo[QKSZ];  // Q split [bh][s][k]
__device__ __nv_bfloat16 g_Khi[QKSZ],  g_Klo[QKSZ];  // K split [bh][s][k]
__device__ __nv_bfloat16 g_xhi[XSZ],   g_xlo[XSZ];   // x split [b][s][d]
__device__ __nv_bfloat16 g_Wthi[WSZ],  g_Wtlo[WSZ];  // W^T split [which][h][k][d]
__device__ __nv_bfloat16 g_WpThi[WPSZ],g_WpTlo[WPSZ];// Wproj^T split [n][hk]
__device__ __nv_bfloat16 g_hhi[XSZ],   g_hlo[XSZ];   // heads split [b][s][hk]
__device__ int g_mma_ok;

// ============================ helpers =======================================
__device__ __forceinline__ uint32_t pk2(float lo_, float hi_){
    uint32_t r;
    asm("cvt.rn.bf16x2.f32 %0, %1, %2;" : "=r"(r) : "f"(hi_), "f"(lo_));
    return r;
}
__device__ __forceinline__ void split8(const float* v, uint4& hi, uint4& lo){
    float h[8];
    #pragma unroll
    for (int i = 0; i < 8; i++) h[i] = __bfloat162float(__float2bfloat16_rn(v[i]));
    hi.x = pk2(h[0], h[1]); hi.y = pk2(h[2], h[3]);
    hi.z = pk2(h[4], h[5]); hi.w = pk2(h[6], h[7]);
    lo.x = pk2(v[0]-h[0], v[1]-h[1]); lo.y = pk2(v[2]-h[2], v[3]-h[3]);
    lo.z = pk2(v[4]-h[4], v[5]-h[5]); lo.w = pk2(v[6]-h[6], v[7]-h[7]);
}
__device__ __forceinline__ void split2(float v0, float v1, uint32_t& hi, uint32_t& lo){
    float h0 = __bfloat162float(__float2bfloat16_rn(v0));
    float h1 = __bfloat162float(__float2bfloat16_rn(v1));
    hi = pk2(h0, h1);
    lo = pk2(v0 - h0, v1 - h1);
}
__device__ __forceinline__ void mma16816(float* c, const uint32_t a[4], const uint32_t b[2]){
    asm volatile("mma.sync.aligned.m16n8k16.row.col.f32.bf16.bf16.f32 "
        "{%0,%1,%2,%3}, {%4,%5,%6,%7}, {%8,%9}, {%0,%1,%2,%3};"
        : "+f"(c[0]), "+f"(c[1]), "+f"(c[2]), "+f"(c[3])
        : "r"(a[0]), "r"(a[1]), "r"(a[2]), "r"(a[3]), "r"(b[0]), "r"(b[1]));
}

// 64-FMA micro-kernel (fp32 fallback path)
#define MICRO_FMA(acc, a0, a1, b0, b1)                                   \
    {                                                                    \
        float _a[8] = {a0.x, a0.y, a0.z, a0.w, a1.x, a1.y, a1.z, a1.w};  \
        float _b[8] = {b0.x, b0.y, b0.z, b0.w, b1.x, b1.y, b1.z, b1.w};  \
        _Pragma("unroll")                                                \
        for (int _i = 0; _i < 8; _i++) {                                 \
            _Pragma("unroll")                                            \
            for (int _j = 0; _j < 8; _j++)                               \
                acc[_i][_j] += _a[_i] * _b[_j];                          \
        }                                                                \
    }

// mma-path smem geometry: rows padded to 80 B -> conflict-free word idx 20r+tg
#define RS2    80
#define A32SZ  (128*RS2)    // 10240
#define B32SZ  (64*RS2)     // 5120
#define SBUF_BYTES (2*A32SZ + 2*B32SZ)   // 30720

__device__ __forceinline__ void frag_a32(uint32_t (&a)[4], const char* base, int row, int kb){
    a[0] = *(const uint32_t*)(base + (size_t)row       * RS2 + kb);
    a[1] = *(const uint32_t*)(base + (size_t)(row + 8) * RS2 + kb);
    a[2] = *(const uint32_t*)(base + (size_t)row       * RS2 + kb + 16);
    a[3] = *(const uint32_t*)(base + (size_t)(row + 8) * RS2 + kb + 16);
}
__device__ __forceinline__ void frag_b32(uint32_t (&b)[2], const char* base, int row, int kb){
    b[0] = *(const uint32_t*)(base + (size_t)row * RS2 + kb);
    b[1] = *(const uint32_t*)(base + (size_t)row * RS2 + kb + 16);
}

// load A chunk (128 rows x 32 k) hi/lo from bf16 global, 128 threads
__device__ __forceinline__ void ldA(char* Ah, char* Al,
        const __nv_bfloat16* sh, const __nv_bfloat16* sl, size_t stride, int k0, int tid){
    #pragma unroll
    for (int i = 0; i < 4; i++){
        int idx = i * 128 + tid;
        int row = idx >> 2, j = idx & 3;
        *(uint4*)(Ah + row * RS2 + j * 16) = *(const uint4*)(sh + (size_t)row * stride + k0 + j * 8);
        *(uint4*)(Al + row * RS2 + j * 16) = *(const uint4*)(sl + (size_t)row * stride + k0 + j * 8);
    }
}
// load B chunk (64 rows x 32 k) hi/lo, 128 threads
__device__ __forceinline__ void ldB(char* Bh, char* Bl,
        const __nv_bfloat16* sh, const __nv_bfloat16* sl, size_t stride, int k0, int tid){
    #pragma unroll
    for (int i = 0; i < 2; i++){
        int idx = i * 128 + tid;
        int row = idx >> 2, j = idx & 3;
        *(uint4*)(Bh + row * RS2 + j * 16) = *(const uint4*)(sh + (size_t)row * stride + k0 + j * 8);
        *(uint4*)(Bl + row * RS2 + j * 16) = *(const uint4*)(sl + (size_t)row * stride + k0 + j * 8);
    }
}
// proven compute core: 128x64x32, 4 warps on M, acc[2][8][4]
__device__ __forceinline__ void compute_chunk(const char* Ah, const char* Al,
        const char* Bh, const char* Bl, int lane, int w, float (&acc)[2][8][4]){
    const int g = lane >> 2, tg = lane & 3;
    #pragma unroll
    for (int ks = 0; ks < 2; ks++){
        const int kb = (ks*16 + tg*2) * 2;
        uint32_t ah[2][4], al[2][4];
        frag_a32(ah[0], Ah, w*32 + g,      kb);
        frag_a32(ah[1], Ah, w*32 + 16 + g, kb);
        frag_a32(al[0], Al, w*32 + g,      kb);
        frag_a32(al[1], Al, w*32 + 16 + g, kb);
        #pragma unroll
        for (int nt = 0; nt < 8; nt++){
            uint32_t bh2[2], bl2[2];
            frag_b32(bh2, Bh, nt*8 + g, kb);
            frag_b32(bl2, Bl, nt*8 + g, kb);
            #pragma unroll
            for (int mt = 0; mt < 2; mt++){
                mma16816(acc[mt][nt], ah[mt], bh2);
                mma16816(acc[mt][nt], ah[mt], bl2);
                mma16816(acc[mt][nt], al[mt], bh2);
            }
        }
    }
}

// ============================================================================
// probe
// ============================================================================
__global__ void mma_probe()
{
    const uint32_t one2 = 0x3F803F80u;
    uint32_t a[4] = {one2, one2, one2, one2};
    uint32_t b[2] = {one2, one2};
    float c[4] = {0.f, 0.f, 0.f, 0.f};
    mma16816(c, a, b);
    bool ok = (c[0] == 16.0f) && (c[1] == 16.0f) && (c[2] == 16.0f) && (c[3] == 16.0f);
    unsigned m = __ballot_sync(0xffffffffu, ok);
    if ((threadIdx.x & 31) == 0) g_mma_ok = (m == 0xffffffffu) ? 1 : 0;
}

// ============================================================================
// prep: elementwise split of x.  grid (XSZ/(256*8)), 256 threads
// ============================================================================
__global__ __launch_bounds__(256) void xsplit_kernel(const float* __restrict__ x)
{
    const size_t i = ((size_t)blockIdx.x * 256 + threadIdx.x) * 8;
    float v[8];
    *(float4*)v     = *(const float4*)(x + i);
    *(float4*)(v+4) = *(const float4*)(x + i + 4);
    uint4 hi, lo; split8(v, hi, lo);
    *(uint4*)(g_xhi + i) = hi;
    *(uint4*)(g_xlo + i) = lo;
}

// ============================================================================
// prep: transpose + split. in [R][C] fp32 (blockIdx.z selects sub-matrix) ->
// out [C][R] bf16 hi/lo.  DESTINATIONS RESOLVED IN DEVICE CODE (the R8-R16
// bug: passing __device__ symbols as host-side kernel args gives the host
// shadow address -> silent writes to nowhere -> zero operands -> bias-only
// output).  sel: 0=W_Q, 1=W_K, 2=W_V (R=Dd,C=Kk), 3=W_proj (R=Dd,C=Dd).
// grid (R/64, C/64, nmat), 256 threads.
// ============================================================================
__global__ __launch_bounds__(256) void tconv_kernel(const float* __restrict__ in,
        int sel, int R, int C)
{
    __nv_bfloat16* ohi;
    __nv_bfloat16* olo;
    if (sel < 3) {
        ohi = g_Wthi + (size_t)sel * Hh * Kk * Dd;
        olo = g_Wtlo + (size_t)sel * Hh * Kk * Dd;
    } else {
        ohi = g_WpThi;
        olo = g_WpTlo;
    }

    __shared__ float ts[64][65];
    const int r0 = blockIdx.x * 64, c0 = blockIdx.y * 64;
    const size_t mb = (size_t)blockIdx.z * R * C;
    in += mb; ohi += mb; olo += mb;
    const int tid = threadIdx.x;
    #pragma unroll
    for (int it = 0; it < 4; it++){
        int idx = it * 256 + tid;
        int r = idx >> 4, c4 = (idx & 15) << 2;
        float4 v = *(const float4*)&in[(size_t)(r0 + r) * C + c0 + c4];
        ts[r][c4] = v.x; ts[r][c4+1] = v.y; ts[r][c4+2] = v.z; ts[r][c4+3] = v.w;
    }
    __syncthreads();
    #pragma unroll
    for (int it = 0; it < 2; it++){
        int idx = it * 256 + tid;
        int oc = idx >> 3, g8 = (idx & 7) << 3;
        float v[8];
        #pragma unroll
        for (int i = 0; i < 8; i++) v[i] = ts[g8 + i][oc];
        uint4 hi, lo; split8(v, hi, lo);
        size_t o = (size_t)(c0 + oc) * R + r0 + g8;
        *(uint4*)(ohi + o) = hi;
        *(uint4*)(olo + o) = lo;
    }
}

// ============================================================================
// qkv via MMA (iff ok). D[s,k]=sum_d x[s,d]W[d,k]+bias. red=1024, 32 chunks.
// grid (16 stile, BH, 3 which), 128 threads
// ============================================================================
__global__ __launch_bounds__(128) void qkv_mma(
    const float* __restrict__ b_Q, const float* __restrict__ b_K,
    const float* __restrict__ b_V)
{
    if (!g_mma_ok) return;
    __shared__ __align__(16) char sbuf[SBUF_BYTES];
    char* Ah = sbuf;          char* Al = sbuf + A32SZ;
    char* Bh = sbuf + 2*A32SZ; char* Bl = sbuf + 2*A32SZ + B32SZ;

    const int tid = threadIdx.x, lane = tid & 31, w = tid >> 5;
    const int s0 = blockIdx.x * 128, bh = blockIdx.y, which = blockIdx.z;
    const int b = bh >> 4, h = bh & 15;

    const __nv_bfloat16* Xh = g_xhi + (size_t)(b * Ss + s0) * Dd;
    const __nv_bfloat16* Xl = g_xlo + (size_t)(b * Ss + s0) * Dd;
    const size_t wo = (size_t)(which * Hh + h) * Kk * Dd;
    const __nv_bfloat16* Wh = g_Wthi + wo;
    const __nv_bfloat16* Wl = g_Wtlo + wo;

    float acc[2][8][4];
    #pragma unroll
    for (int i = 0; i < 2; i++)
        #pragma unroll
        for (int j = 0; j < 8; j++)
            #pragma unroll
            for (int k = 0; k < 4; k++) acc[i][j][k] = 0.f;

    for (int c = 0; c < 32; c++){
        const int k0 = c * 32;
        ldA(Ah, Al, Xh, Xl, Dd, k0, tid);
        ldB(Bh, Bl, Wh, Wl, Dd, k0, tid);
        __syncthreads();
        compute_chunk(Ah, Al, Bh, Bl, lane, w, acc);
        __syncthreads();
    }

    const float* bias = (which == 0) ? b_Q : (which == 1) ? b_K : b_V;
    float* out = (which == 0) ? g_Q : (which == 1) ? g_K : g_V;
    const int g = lane >> 2, tg = lane & 3;
    #pragma unroll
    for (int mt = 0; mt < 2; mt++)
        #pragma unroll
        for (int nt = 0; nt < 8; nt++){
            const int cc = nt * 8 + tg * 2;
            const float bv0 = bias[h * Kk + cc], bv1 = bias[h * Kk + cc + 1];
            #pragma unroll
            for (int p = 0; p < 2; p++){
                const int r = s0 + w * 32 + mt * 16 + g + p * 8;
                float2 o;
                o.x = acc[mt][nt][p*2]   + bv0;
                o.y = acc[mt][nt][p*2+1] + bv1;
                *(float2*)&out[((size_t)bh * Ss + r) * Kk + cc] = o;
            }
        }
}

// ============================================================================
// qkv fp32 fallback (iff !ok)
// ============================================================================
__global__ __launch_bounds__(128) void qkv_kernel(
    const float* __restrict__ x,
    const float* __restrict__ W_Q, const float* __restrict__ b_Q,
    const float* __restrict__ W_K, const float* __restrict__ b_K,
    const float* __restrict__ W_V, const float* __restrict__ b_V)
{
    if (g_mma_ok) return;
    const int stile = blockIdx.x;
    const int bh    = blockIdx.y;
    const int which = blockIdx.z;
    const int b = bh / Hh, h = bh % Hh;

    const float* W    = (which == 0) ? W_Q : (which == 1) ? W_K : W_V;
    const float* bias = (which == 0) ? b_Q : (which == 1) ? b_K : b_V;
    float*       out  = (which == 0) ? g_Q : (which == 1) ? g_K : g_V;

    __shared__ float At[32][132];
    __shared__ float Bs[32][68];

    const int tid = threadIdx.x;
    const int s0 = stile * 128;
    const float* Ax = x + ((size_t)b * Ss + s0) * Dd;
    const float* Wh = W + (size_t)h * Dd * Kk;

    const int r0 = (tid >> 3) << 3;
    const int c0 = (tid & 7) << 3;

    float acc[8][8];
    #pragma unroll
    for (int i = 0; i < 8; i++)
        #pragma unroll
        for (int j = 0; j < 8; j++) acc[i][j] = 0.f;

    for (int d0 = 0; d0 < Dd; d0 += 32) {
        #pragma unroll
        for (int it = 0; it < 8; it++) {
            const int idx = it * 128 + tid;
            const int row = idx >> 3;
            const int k4  = (idx & 7) << 2;
            const float4 v = *(const float4*)&Ax[(size_t)row * Dd + d0 + k4];
            At[k4 + 0][row] = v.x; At[k4 + 1][row] = v.y;
            At[k4 + 2][row] = v.z; At[k4 + 3][row] = v.w;
        }
        #pragma unroll
        for (int it = 0; it < 4; it++) {
            const int idx = it * 128 + tid;
            const int dd = idx >> 4;
            const int c4 = (idx & 15) << 2;
            *(float4*)&Bs[dd][c4] = *(const float4*)&Wh[(size_t)(d0 + dd) * Kk + c4];
        }
        __syncthreads();
        #pragma unroll
        for (int dd = 0; dd < 32; dd++) {
            const float4 a0 = *(const float4*)&At[dd][r0];
            const float4 a1 = *(const float4*)&At[dd][r0 + 4];
            const float4 b0 = *(const float4*)&Bs[dd][c0];
            const float4 b1 = *(const float4*)&Bs[dd][c0 + 4];
            MICRO_FMA(acc, a0, a1, b0, b1);
        }
        __syncthreads();
    }

    float bv[8];
    #pragma unroll
    for (int j = 0; j < 8; j++) bv[j] = bias[h * Kk + c0 + j];

    float* outp = out + ((size_t)bh * Ss + s0) * Kk;
    #pragma unroll
    for (int i = 0; i < 8; i++) {
        float4 o0, o1;
        o0.x = acc[i][0] + bv[0]; o0.y = acc[i][1] + bv[1];
        o0.z = acc[i][2] + bv[2]; o0.w = acc[i][3] + bv[3];
        o1.x = acc[i][4] + bv[4]; o1.y = acc[i][5] + bv[5];
        o1.z = acc[i][6] + bv[6]; o1.w = acc[i][7] + bv[7];
        *(float4*)&outp[(size_t)(r0 + i) * Kk + c0]     = o0;
        *(float4*)&outp[(size_t)(r0 + i) * Kk + c0 + 4] = o1;
    }
}

// ============================================================================
// qksplit: split g_Q / g_K.  grid (QKSZ/(256*8), 2), 256 threads
// ============================================================================
__global__ __launch_bounds__(256) void qksplit_kernel()
{
    const size_t i = ((size_t)blockIdx.x * 256 + threadIdx.x) * 8;
    const float* src = (blockIdx.y == 0) ? g_Q : g_K;
    __nv_bfloat16* dhi = (blockIdx.y == 0) ? g_Qhi : g_Khi;
    __nv_bfloat16* dlo = (blockIdx.y == 0) ? g_Qlo : g_Klo;
    float v[8];
    *(float4*)v     = *(const float4*)(src + i);
    *(float4*)(v+4) = *(const float4*)(src + i + 4);
    uint4 hi, lo; split8(v, hi, lo);
    *(uint4*)(dhi + i) = hi;
    *(uint4*)(dlo + i) = lo;
}

// ============================================================================
// scores via MMA (iff ok).  grid (32 ttile, 16 stile, BH), 128 threads
// ============================================================================
__global__ __launch_bounds__(128) void scores_mma(
    const int* __restrict__ mask, float* __restrict__ out_scores)
{
    if (!g_mma_ok) return;
    __shared__ __align__(16) char sbuf[SBUF_BYTES];
    char* Ah = sbuf;          char* Al = sbuf + A32SZ;
    char* Bh = sbuf + 2*A32SZ; char* Bl = sbuf + 2*A32SZ + B32SZ;

    const int tid = threadIdx.x, lane = tid & 31, w = tid >> 5;
    const int t0 = blockIdx.x * 64;
    const int s0 = blockIdx.y * 128;
    const int bh = blockIdx.z;
    const int b  = bh >> 4;

    const __nv_bfloat16* Qh = g_Qhi + (size_t)(bh * Ss + s0) * Kk;
    const __nv_bfloat16* Ql = g_Qlo + (size_t)(bh * Ss + s0) * Kk;
    const __nv_bfloat16* Kh = g_Khi + (size_t)(bh * Ss + t0) * Kk;
    const __nv_bfloat16* Kl = g_Klo + (size_t)(bh * Ss + t0) * Kk;

    float acc[2][8][4];
    #pragma unroll
    for (int i = 0; i < 2; i++)
        #pragma unroll
        for (int j = 0; j < 8; j++)
            #pragma unroll
            for (int k = 0; k < 4; k++) acc[i][j][k] = 0.f;

    #pragma unroll
    for (int c = 0; c < 2; c++){
        const int k0 = c * 32;
        ldA(Ah, Al, Qh, Ql, Kk, k0, tid);
        ldB(Bh, Bl, Kh, Kl, Kk, k0, tid);
        __syncthreads();
        compute_chunk(Ah, Al, Bh, Bl, lane, w, acc);
        __syncthreads();
    }

    const int g = lane >> 2, tg = lane & 3;
    #pragma unroll
    for (int mt = 0; mt < 2; mt++)
        #pragma unroll
        for (int p = 0; p < 2; p++){
            const int r = s0 + w * 32 + mt * 16 + g + p * 8;
            const int* mrow = mask + ((size_t)b * Ss + r) * Ss + t0;
            float* orow = out_scores + ((size_t)bh * Ss + r) * Ss + t0;
            #pragma unroll
            for (int nt = 0; nt < 8; nt++){
                const int cc = nt * 8 + tg * 2;
                const int2 m = *(const int2*)(mrow + cc);
                float2 o;
                o.x = m.x ? acc[mt][nt][p*2]   * SCALE : NEGF;
                o.y = m.y ? acc[mt][nt][p*2+1] * SCALE : NEGF;
                *(float2*)(orow + cc) = o;
            }
        }
}

// ============================================================================
// scores fp32 fallback (iff !ok)
// ============================================================================
__global__ __launch_bounds__(256) void scores_kernel(
    const int* __restrict__ mask, float* __restrict__ out_scores)
{
    if (g_mma_ok) return;
    extern __shared__ float sm[];
    float (*Qt)[132] = (float(*)[132])sm;
    float (*Kt)[132] = (float(*)[132])(sm + 64 * 132);

    const int h  = blockIdx.x;
    const int b  = blockIdx.z;
    const int bh = b * Hh + h;
    const int st = blockIdx.y & 15;
    const int tt = blockIdx.y >> 4;
    const int s0 = st * 128;
    const int t0 = tt * 128;
    const int tid = threadIdx.x;

    const float* Qg = g_Q + ((size_t)bh * Ss + s0) * Kk;
    const float* Kg = g_K + ((size_t)bh * Ss + t0) * Kk;

    #pragma unroll
    for (int it = 0; it < 8; it++) {
        const int idx = it * 256 + tid;
        const int row = idx >> 4;
        const int k4  = (idx & 15) << 2;
        const float4 q = *(const float4*)&Qg[(size_t)row * Kk + k4];
        Qt[k4 + 0][row] = q.x; Qt[k4 + 1][row] = q.y;
        Qt[k4 + 2][row] = q.z; Qt[k4 + 3][row] = q.w;
        const float4 k = *(const float4*)&Kg[(size_t)row * Kk + k4];
        Kt[k4 + 0][row] = k.x; Kt[k4 + 1][row] = k.y;
        Kt[k4 + 2][row] = k.z; Kt[k4 + 3][row] = k.w;
    }
    __syncthreads();

    const int r0 = (tid >> 4) << 3;
    const int c0 = (tid & 15) << 3;

    float acc[8][8];
    #pragma unroll
    for (int i = 0; i < 8; i++)
        #pragma unroll
        for (int j = 0; j < 8; j++) acc[i][j] = 0.f;

    #pragma unroll 8
    for (int k = 0; k < Kk; k++) {
        const float4 a0 = *(const float4*)&Qt[k][r0];
        const float4 a1 = *(const float4*)&Qt[k][r0 + 4];
        const float4 b0 = *(const float4*)&Kt[k][c0];
        const float4 b1 = *(const float4*)&Kt[k][c0 + 4];
        MICRO_FMA(acc, a0, a1, b0, b1);
    }

    #pragma unroll
    for (int i = 0; i < 8; i++) {
        const int s = s0 + r0 + i;
        const int* mrow = mask + ((size_t)b * Ss + s) * Ss + t0;
        const int4 m0 = *(const int4*)&mrow[c0];
        const int4 m1 = *(const int4*)&mrow[c0 + 4];
        float4 o0, o1;
        o0.x = m0.x ? acc[i][0] * SCALE : NEGF;
        o0.y = m0.y ? acc[i][1] * SCALE : NEGF;
        o0.z = m0.z ? acc[i][2] * SCALE : NEGF;
        o0.w = m0.w ? acc[i][3] * SCALE : NEGF;
        o1.x = m1.x ? acc[i][4] * SCALE : NEGF;
        o1.y = m1.y ? acc[i][5] * SCALE : NEGF;
        o1.z = m1.z ? acc[i][6] * SCALE : NEGF;
        o1.w = m1.w ? acc[i][7] * SCALE : NEGF;
        float* orow = out_scores + ((size_t)bh * Ss + s) * Ss + t0;
        *(float4*)&orow[c0]     = o0;
        *(float4*)&orow[c0 + 4] = o1;
    }
}

// ============================================================================
// softmax (R5 verbatim)
// ============================================================================
__global__ __launch_bounds__(256) void softmax_kernel(float* __restrict__ scores)
{
    __shared__ float red[8];
    __shared__ float bcast;

    float4* row = (float4*)(scores + (size_t)blockIdx.x * Ss);
    const int tid = threadIdx.x;
    const int lane = tid & 31, warp = tid >> 5;

    float4 v0 = row[tid];
    float4 v1 = row[tid + 256];

    float mx = fmaxf(fmaxf(fmaxf(v0.x, v0.y), fmaxf(v0.z, v0.w)),
                     fmaxf(fmaxf(v1.x, v1.y), fmaxf(v1.z, v1.w)));
    #pragma unroll
    for (int o = 16; o > 0; o >>= 1) mx = fmaxf(mx, __shfl_xor_sync(0xffffffffu, mx, o));
    if (lane == 0) red[warp] = mx;
    __syncthreads();
    if (tid == 0) {
        float m = red[0];
        #pragma unroll
        for (int i = 1; i < 8; i++) m = fmaxf(m, red[i]);
        bcast = m;
    }
    __syncthreads();
    mx = bcast;

    v0.x = __expf(v0.x - mx); v0.y = __expf(v0.y - mx);
    v0.z = __expf(v0.z - mx); v0.w = __expf(v0.w - mx);
    v1.x = __expf(v1.x - mx); v1.y = __expf(v1.y - mx);
    v1.z = __expf(v1.z - mx); v1.w = __expf(v1.w - mx);
    float sum = v0.x + v0.y + v0.z + v0.w + v1.x + v1.y + v1.z + v1.w;
    #pragma unroll
    for (int o = 16; o > 0; o >>= 1) sum += __shfl_xor_sync(0xffffffffu, sum, o);
    __syncthreads();
    if (lane == 0) red[warp] = sum;
    __syncthreads();
    if (tid == 0) {
        float s = 0.f;
        #pragma unroll
        for (int i = 0; i < 8; i++) s += red[i];
        bcast = 1.0f / s;
    }
    __syncthreads();
    const float inv = bcast;

    v0.x *= inv; v0.y *= inv; v0.z *= inv; v0.w *= inv;
    v1.x *= inv; v1.y *= inv; v1.z *= inv; v1.w *= inv;
    row[tid]       = v0;
    row[tid + 256] = v1;
}

// ============================================================================
// vsplit: transpose+split g_V -> Vt hi/lo.  grid (32, BH), 256 threads
// ============================================================================
__global__ __launch_bounds__(256) void vsplit_kernel()
{
    __shared__ float ts[64][65];
    const int s0 = blockIdx.x * 64;
    const int bh = blockIdx.y;
    const float* src = g_V + ((size_t)bh * Ss + s0) * Kk;
    const int tid = threadIdx.x;
    #pragma unroll
    for (int it = 0; it < 4; it++){
        int idx = it * 256 + tid;
        int r = idx >> 4;
        int c4 = (idx & 15) << 2;
        float4 v = *(const float4*)&src[(size_t)r * Kk + c4];
        ts[r][c4] = v.x; ts[r][c4+1] = v.y; ts[r][c4+2] = v.z; ts[r][c4+3] = v.w;
    }
    __syncthreads();
    #pragma unroll
    for (int it = 0; it < 2; it++){
        int idx = it * 256 + tid;
        int k = idx >> 3;
        int g8 = (idx & 7) << 3;
        float v[8];
        #pragma unroll
        for (int i = 0; i < 8; i++) v[i] = ts[g8 + i][k];
        uint4 hi, lo; split8(v, hi, lo);
        size_t o = ((size_t)bh * Kk + k) * Ss + s0 + g8;
        *(uint4*)(g_Vthi + o) = hi;
        *(uint4*)(g_Vtlo + o) = lo;
    }
}

// ============================================================================
// pv_dual — heads = P @ V.  MMA path writes split heads; fallback fp32.
// grid (16, BH), 128 threads
// ============================================================================
__global__ __launch_bounds__(128) void pv_dual(const float* __restrict__ probs)
{
    __shared__ __align__(16) char sbuf[SBUF_BYTES];

    const int bh = blockIdx.y;
    const int b = bh / Hh, h = bh % Hh;
    const int s0 = blockIdx.x * 128;
    const int tid = threadIdx.x;

    const float* Pg = probs + ((size_t)bh * Ss + s0) * Ss;

    if (g_mma_ok) {
        const int lane = tid & 31, w = tid >> 5;
        char* Ah = sbuf;          char* Al = sbuf + A32SZ;
        char* Bh = sbuf + 2*A32SZ; char* Bl = sbuf + 2*A32SZ + B32SZ;

        const __nv_bfloat16* Vh = g_Vthi + (size_t)bh * Kk * Ss;
        const __nv_bfloat16* Vl = g_Vtlo + (size_t)bh * Kk * Ss;

        float acc[2][8][4];
        #pragma unroll
        for (int i = 0; i < 2; i++)
            #pragma unroll
            for (int j = 0; j < 8; j++)
                #pragma unroll
                for (int k = 0; k < 4; k++) acc[i][j][k] = 0.f;

        const int g = lane >> 2, tg = lane & 3;

        for (int c = 0; c < 64; c++){
            const int t0 = c * 32;
            #pragma unroll
            for (int i = 0; i < 4; i++){
                int idx = i * 128 + tid;
                int row = idx >> 2, gq = idx & 3;
                float v[8];
                const float* src = Pg + (size_t)row * Ss + t0 + gq * 8;
                *(float4*)v       = *(const float4*)src;
                *(float4*)(v + 4) = *(const float4*)(src + 4);
                uint4 hi, lo; split8(v, hi, lo);
                *(uint4*)(Ah + row * RS2 + gq * 16) = hi;
                *(uint4*)(Al + row * RS2 + gq * 16) = lo;
            }
            ldB(Bh, Bl, Vh, Vl, Ss, t0, tid);
            __syncthreads();
            compute_chunk(Ah, Al, Bh, Bl, lane, w, acc);
            __syncthreads();
        }

        #pragma unroll
        for (int mt = 0; mt < 2; mt++)
            #pragma unroll
            for (int nt = 0; nt < 8; nt++){
                const int cc = nt * 8 + tg * 2;
                #pragma unroll
                for (int p = 0; p < 2; p++){
                    const int r = s0 + w * 32 + mt * 16 + g + p * 8;
                    uint32_t hi, lo;
                    split2(acc[mt][nt][p*2], acc[mt][nt][p*2+1], hi, lo);
                    const size_t o = ((size_t)(b * Ss + r)) * (Hh * Kk) + h * Kk + cc;
                    *(uint32_t*)(g_hhi + o) = hi;
                    *(uint32_t*)(g_hlo + o) = lo;
                }
            }
    } else {
        float (*Pt)[132] = (float(*)[132])sbuf;
        float (*Vs)[68]  = (float(*)[68])(sbuf + 16896);

        const float* Vg = g_V + (size_t)bh * Ss * Kk;

        const int r0 = (tid >> 3) << 3;
        const int c0 = (tid & 7) << 3;

        float acc[8][8];
        #pragma unroll
        for (int i = 0; i < 8; i++)
            #pragma unroll
            for (int j = 0; j < 8; j++) acc[i][j] = 0.f;

        for (int t0 = 0; t0 < Ss; t0 += 32) {
            #pragma unroll
            for (int it = 0; it < 8; it++) {
                const int idx = it * 128 + tid;
                const int row = idx >> 3;
                const int q4  = (idx & 7) << 2;
                const float4 v = *(const float4*)&Pg[(size_t)row * Ss + t0 + q4];
                Pt[q4 + 0][row] = v.x; Pt[q4 + 1][row] = v.y;
                Pt[q4 + 2][row] = v.z; Pt[q4 + 3][row] = v.w;
            }
            #pragma unroll
            for (int it = 0; it < 4; it++) {
                const int idx = it * 128 + tid;
                const int tt = idx >> 4;
                const int c4 = (idx & 15) << 2;
                *(float4*)&Vs[tt][c4] = *(const float4*)&Vg[(size_t)(t0 + tt) * Kk + c4];
            }
            __syncthreads();
            #pragma unroll
            for (int tt = 0; tt < 32; tt++) {
                const float4 a0 = *(const float4*)&Pt[tt][r0];
                const float4 a1 = *(const float4*)&Pt[tt][r0 + 4];
                const float4 b0 = *(const float4*)&Vs[tt][c0];
                const float4 b1 = *(const float4*)&Vs[tt][c0 + 4];
                MICRO_FMA(acc, a0, a1, b0, b1);
            }
            __syncthreads();
        }

        #pragma unroll
        for (int i = 0; i < 8; i++) {
            float* orow = g_heads + ((size_t)(b * Ss + s0 + r0 + i)) * (Hh * Kk) + h * Kk;
            float4 o0, o1;
            o0.x = acc[i][0]; o0.y = acc[i][1]; o0.z = acc[i][2]; o0.w = acc[i][3];
            o1.x = acc[i][4]; o1.y = acc[i][5]; o1.z = acc[i][6]; o1.w = acc[i][7];
            *(float4*)&orow[c0]     = o0;
            *(float4*)&orow[c0 + 4] = o1;
        }
    }
}

// ============================================================================
// proj via MMA (iff ok).  grid (16 ntile, 32 mtile), 128 threads
// ============================================================================
__global__ __launch_bounds__(128) void proj_mma(
    const float* __restrict__ bp, float* __restrict__ out)
{
    if (!g_mma_ok) return;
    __shared__ __align__(16) char sbuf[SBUF_BYTES];
    char* Ah = sbuf;          char* Al = sbuf + A32SZ;
    char* Bh = sbuf + 2*A32SZ; char* Bl = sbuf + 2*A32SZ + B32SZ;

    const int tid = threadIdx.x, lane = tid & 31, w = tid >> 5;
    const int n0 = blockIdx.x * 64, m0 = blockIdx.y * 128;

    const __nv_bfloat16* Hhp = g_hhi + (size_t)m0 * Dd;
    const __nv_bfloat16* Hlp = g_hlo + (size_t)m0 * Dd;
    const __nv_bfloat16* Wh = g_WpThi + (size_t)n0 * Dd;
    const __nv_bfloat16* Wl = g_WpTlo + (size_t)n0 * Dd;

    float acc[2][8][4];
    #pragma unroll
    for (int i = 0; i < 2; i++)
        #pragma unroll
        for (int j = 0; j < 8; j++)
            #pragma unroll
            for (int k = 0; k < 4; k++) acc[i][j][k] = 0.f;

    for (int c = 0; c < 32; c++){
        const int k0 = c * 32;
        ldA(Ah, Al, Hhp, Hlp, Dd, k0, tid);
        ldB(Bh, Bl, Wh, Wl, Dd, k0, tid);
        __syncthreads();
        compute_chunk(Ah, Al, Bh, Bl, lane, w, acc);
        __syncthreads();
    }

    const int g = lane >> 2, tg = lane & 3;
    #pragma unroll
    for (int mt = 0; mt < 2; mt++)
        #pragma unroll
        for (int nt = 0; nt < 8; nt++){
            const int cc = nt * 8 + tg * 2;
            const float bv0 = bp[n0 + cc], bv1 = bp[n0 + cc + 1];
            #pragma unroll
            for (int p = 0; p < 2; p++){
                const int r = m0 + w * 32 + mt * 16 + g + p * 8;
                float2 o;
                o.x = acc[mt][nt][p*2]   + bv0;
                o.y = acc[mt][nt][p*2+1] + bv1;
                *(float2*)(out + (size_t)r * Dd + n0 + cc) = o;
            }
        }
}

// ============================================================================
// proj fp32 fallback (iff !ok)
// ============================================================================
__global__ __launch_bounds__(128) void proj_kernel(
    const float* __restrict__ Wp, const float* __restrict__ bp,
    float* __restrict__ out)
{
    if (g_mma_ok) return;
    __shared__ float At[32][132];
    __shared__ float Bs[32][68];

    const int tid = threadIdx.x;
    const int n0 = blockIdx.x * 64;
    const int m0 = blockIdx.y * 128;
    const int HK = Hh * Kk;

    const float* A = g_heads + (size_t)m0 * HK;

    const int r0 = (tid >> 3) << 3;
    const int c0 = (tid & 7) << 3;

    float acc[8][8];
    #pragma unroll
    for (int i = 0; i < 8; i++)
        #pragma unroll
        for (int j = 0; j < 8; j++) acc[i][j] = 0.f;

    for (int d0 = 0; d0 < HK; d0 += 32) {
        #pragma unroll
        for (int it = 0; it < 8; it++) {
            const int idx = it * 128 + tid;
            const int row = idx >> 3;
            const int k4  = (idx & 7) << 2;
            const float4 v = *(const float4*)&A[(size_t)row * HK + d0 + k4];
            At[k4 + 0][row] = v.x; At[k4 + 1][row] = v.y;
            At[k4 + 2][row] = v.z; At[k4 + 3][row] = v.w;
        }
        #pragma unroll
        for (int it = 0; it < 4; it++) {
            const int idx = it * 128 + tid;
            const int dd = idx >> 4;
            const int c4 = (idx & 15) << 2;
            *(float4*)&Bs[dd][c4] = *(const float4*)&Wp[(size_t)(d0 + dd) * Dd + n0 + c4];
        }
        __syncthreads();
        #pragma unroll
        for (int dd = 0; dd < 32; dd++) {
            const float4 a0 = *(const float4*)&At[dd][r0];
            const float4 a1 = *(const float4*)&At[dd][r0 + 4];
            const float4 b0 = *(const float4*)&Bs[dd][c0];
            const float4 b1 = *(const float4*)&Bs[dd][c0 + 4];
            MICRO_FMA(acc, a0, a1, b0, b1);
        }
        __syncthreads();
    }

    float bv[8];
    #pragma unroll
    for (int j = 0; j < 8; j++) bv[j] = bp[n0 + c0 + j];

    #pragma unroll
    for (int i = 0; i < 8; i++) {
        float4 o0, o1;
        o0.x = acc[i][0] + bv[0]; o0.y = acc[i][1] + bv[1];
        o0.z = acc[i][2] + bv[2]; o0.w = acc[i][3] + bv[3];
        o1.x = acc[i][4] + bv[4]; o1.y = acc[i][5] + bv[5];
        o1.z = acc[i][6] + bv[6]; o1.w = acc[i][7] + bv[7];
        *(float4*)&out[(size_t)(m0 + r0 + i) * Dd + n0 + c0]     = o0;
        *(float4*)&out[(size_t)(m0 + r0 + i) * Dd + n0 + c0 + 4] = o1;
    }
}

// ============================================================================
extern "C" void kernel_launch(void* const* d_in, const int* in_sizes, int n_in,
                              void* d_out, int out_size)
{
    const float* x      = (const float*)d_in[0];
    const float* W_Q    = (const float*)d_in[1];
    const float* b_Q    = (const float*)d_in[2];
    const float* W_K    = (const float*)d_in[3];
    const float* b_K    = (const float*)d_in[4];
    const float* W_V    = (const float*)d_in[5];
    const float* b_V    = (const float*)d_in[6];
    const float* W_proj = (const float*)d_in[7];
    const float* b_proj = (const float*)d_in[8];
    const int*   amask  = (const int*)d_in[9];

    float* out        = (float*)d_out;                  // [B,S,D]
    float* out_scores = out + (size_t)Bb * Ss * Dd;     // [B,H,S,S]

    // 0) probe mma.sync
    mma_probe<<<1, 32>>>();

    // prep: split x; transpose+split weights (destinations resolved in-kernel)
    xsplit_kernel<<<(int)(XSZ / (256 * 8)), 256>>>(x);
    tconv_kernel<<<dim3(16, 1, 16), 256>>>(W_Q,    0, Dd, Kk);
    tconv_kernel<<<dim3(16, 1, 16), 256>>>(W_K,    1, Dd, Kk);
    tconv_kernel<<<dim3(16, 1, 16), 256>>>(W_V,    2, Dd, Kk);
    tconv_kernel<<<dim3(16, 16, 1), 256>>>(W_proj, 3, Dd, Dd);

    // 1) QKV — dual path
    qkv_mma<<<dim3(16, BH, 3), 128>>>(b_Q, b_K, b_V);
    qkv_kernel<<<dim3(16, BH, 3), 128>>>(x, W_Q, b_Q, W_K, b_K, W_V, b_V);

    // 1b) split Q/K for mma scores
    qksplit_kernel<<<dim3((int)(QKSZ / (256 * 8)), 2), 256>>>();

    // 2) scores — dual path
    scores_mma<<<dim3(Ss / 64, 16, BH), 128>>>(amask, out_scores);
    {
        const int smem = 2 * 64 * 132 * (int)sizeof(float);
        cudaFuncSetAttribute(scores_kernel, cudaFuncAttributeMaxDynamicSharedMemorySize, smem);
        scores_kernel<<<dim3(Hh, 256, Bb), 256, smem>>>(amask, out_scores);
    }

    // 3) softmax (normalized P = output 1)
    softmax_kernel<<<BH * Ss, 256>>>(out_scores);

    // 3b) V transpose + split
    vsplit_kernel<<<dim3(Ss / 64, BH), 256>>>();

    // 4) P @ V — dual path (mma epilogue writes split heads)
    pv_dual<<<dim3(16, BH), 128>>>(out_scores);

    // 5) projection — dual path
    proj_mma<<<dim3(16, 32), 128>>>(b_proj, out);
    proj_kernel<<<dim3(16, (Bb * Ss) / 128), 128>>>(W_proj, b_proj, out);
}